// round 2
// baseline (speedup 1.0000x reference)
#include <cuda_runtime.h>
#include <math.h>

#define NB 256
#define NC 26
#define SXv 179
#define SYv 15
#define NP (SXv*SYv)          // 2685
#define MM 7
#define NMODE (14*MM)         // 98
#define KTOT (NC*NP)          // 69810
#define NH1 2808
#define NO 128

// ---------------- device scratch ----------------
__device__ float  g_h [NB*NC*NP];
__device__ float  g_t1[NB*NC*NP];
__device__ float  g_t2[NB*NC*NP];
__device__ float2 g_F [NB*NC*NMODE];
__device__ float2 g_G [NB*NC*NMODE];
__device__ float2 g_twx[8*SXv];
__device__ float2 g_twy[MM*SYv];
__device__ float  g_ap [NB*NC];
__device__ float  g_att[NB];
__device__ float  g_Cp [2*NB*NH1];   // gemm1 partials; reused for gemm2 partials (8*NB*NO fits)
__device__ float  g_C  [NB*NH1];
__device__ float  g_x1 [NB*NO];

__device__ __forceinline__ float gelu_f(float x){
    return 0.5f*x*(1.0f + erff(x*0.70710678118654752f));
}

// ---------------- twiddle tables ----------------
__global__ void k_twiddle(){
    int i = blockIdx.x*blockDim.x + threadIdx.x;
    if (i < 8*SXv){
        int k = i/SXv, xx = i%SXv;
        float sn, cs;
        sincospif(2.0f*(float)(k*xx)/179.0f, &sn, &cs);
        g_twx[i] = make_float2(cs, sn);
    }
    if (i < MM*SYv){
        int k = i/SYv, y = i%SYv;
        float sn, cs;
        sincospif(2.0f*(float)(k*y)/15.0f, &sn, &cs);
        g_twy[i] = make_float2(cs, sn);
    }
}

// ---------------- lift ----------------
__global__ void k_build(const float* __restrict__ x,
                        const float* __restrict__ pw,
                        const float* __restrict__ pb){
    int bc = blockIdx.x;
    int b = bc / NC, w = bc % NC;
    float w0 = pw[w*3+0], w1 = pw[w*3+1], w2 = pw[w*3+2], bb = pb[w];
    const float* xb = x + (size_t)b*SXv*(SYv+1);
    float* out = g_h + (size_t)bc*NP;
    for (int p = threadIdx.x; p < NP; p += blockDim.x){
        int xi = p/SYv, yi = p%SYv;
        float u = xb[xi*(SYv+1) + yi];
        out[p] = u*w0 + ((float)xi*(1.0f/178.0f))*w1 + ((float)yi*(1.0f/14.0f))*w2 + bb;
    }
}

// ---------------- instance norm ----------------
__global__ void k_inorm(int mode){   // 0: g_h->g_t1, 1: g_t1->g_t2
    const float* s = (mode ? g_t1 : g_h) + (size_t)blockIdx.x*NP;
    float* d = (mode ? g_t2 : g_t1) + (size_t)blockIdx.x*NP;
    __shared__ float rs[256], rq[256];
    float sum = 0.f, sq = 0.f;
    for (int p = threadIdx.x; p < NP; p += 256){ float v = s[p]; sum += v; sq += v*v; }
    rs[threadIdx.x] = sum; rq[threadIdx.x] = sq;
    __syncthreads();
    for (int o = 128; o > 0; o >>= 1){
        if (threadIdx.x < o){ rs[threadIdx.x] += rs[threadIdx.x+o]; rq[threadIdx.x] += rq[threadIdx.x+o]; }
        __syncthreads();
    }
    float mu  = rs[0] * (1.0f/NP);
    float var = rq[0] * (1.0f/NP) - mu*mu;
    float inv = rsqrtf(var + 1e-5f);
    for (int p = threadIdx.x; p < NP; p += 256) d[p] = (s[p]-mu)*inv;
}

// ---------------- forward truncated DFT (g_t1 -> g_F) ----------------
__global__ void k_fdft(){
    int bc = blockIdx.x;
    __shared__ float  sp[NP];
    __shared__ float2 Ys[SXv*MM];
    const float* s = g_t1 + (size_t)bc*NP;
    for (int p = threadIdx.x; p < NP; p += 256) sp[p] = s[p];
    __syncthreads();
    for (int idx = threadIdx.x; idx < SXv*MM; idx += 256){
        int xx = idx/MM, k2 = idx%MM;
        float re = 0.f, im = 0.f;
        #pragma unroll
        for (int y = 0; y < SYv; y++){
            float2 t = g_twy[k2*SYv + y];
            float v = sp[xx*SYv + y];
            re = fmaf(v, t.x, re);
            im = fmaf(v, -t.y, im);
        }
        Ys[idx] = make_float2(re, im);
    }
    __syncthreads();
    for (int mode = threadIdx.x; mode < NMODE; mode += 256){
        int k1i = mode/MM, k2 = mode%MM;
        const float2* tw = g_twx + ((k1i < 7) ? k1i : (14-k1i))*SXv;
        float sgn = (k1i < 7) ? -1.f : 1.f;
        float re = 0.f, im = 0.f;
        #pragma unroll 4
        for (int xx = 0; xx < SXv; xx++){
            float2 u = tw[xx];
            float tc = u.x, ts = sgn*u.y;
            float2 y = Ys[xx*MM + k2];
            re += y.x*tc - y.y*ts;
            im += y.x*ts + y.y*tc;
        }
        g_F[(size_t)bc*NMODE + mode] = make_float2(re, im);
    }
}

// ---------------- complex channel mix (g_F -> g_G) ----------------
__global__ void k_mix(const float* __restrict__ w1, const float* __restrict__ w2){
    int b = blockIdx.x;
    __shared__ float2 Fs[NC*NMODE];
    for (int i = threadIdx.x; i < NC*NMODE; i += 256)
        Fs[i] = g_F[(size_t)b*NC*NMODE + i];
    __syncthreads();
    for (int oi = threadIdx.x; oi < NC*NMODE; oi += 256){
        int o = oi/NMODE, mode = oi%NMODE;
        int k1i = mode/MM, k2 = mode%MM;
        const float* wp;
        if (k1i < 7) wp = w1 + ((size_t)(o*MM + k1i)*MM + k2)*2;
        else         wp = w2 + ((size_t)(o*MM + (k1i-7))*MM + k2)*2;
        float re = 0.f, im = 0.f;
        #pragma unroll 2
        for (int i = 0; i < NC; i++){
            float2 f = Fs[i*NMODE + mode];
            float wr = wp[0], wi = wp[1];
            re += f.x*wr - f.y*wi;
            im += f.x*wi + f.y*wr;
            wp += NC*MM*MM*2;
        }
        g_G[(size_t)b*NC*NMODE + oi] = make_float2(re, im);
    }
}

// ---------------- inverse truncated DFT (g_G -> g_t1) ----------------
__global__ void k_idft(){
    int bc = blockIdx.x;
    __shared__ float2 Gs[NMODE];
    __shared__ float2 Ss[SXv*MM];
    for (int i = threadIdx.x; i < NMODE; i += 256)
        Gs[i] = g_G[(size_t)bc*NMODE + i];
    __syncthreads();
    for (int idx = threadIdx.x; idx < SXv*MM; idx += 256){
        int n1 = idx/MM, k2 = idx%MM;
        float re = 0.f, im = 0.f;
        #pragma unroll
        for (int k1i = 0; k1i < 14; k1i++){
            float2 g = Gs[k1i*MM + k2];
            float2 u = (k1i < 7) ? g_twx[k1i*SXv + n1] : g_twx[(14-k1i)*SXv + n1];
            float ts = (k1i < 7) ? u.y : -u.y;
            re += g.x*u.x - g.y*ts;
            im += g.x*ts + g.y*u.x;
        }
        Ss[idx] = make_float2(re, im);
    }
    __syncthreads();
    float* d = g_t1 + (size_t)bc*NP;
    for (int p = threadIdx.x; p < NP; p += 256){
        int n1 = p/SYv, n2 = p%SYv;
        float val = Ss[n1*MM].x;
        #pragma unroll
        for (int k2 = 1; k2 < MM; k2++){
            float2 s = Ss[n1*MM + k2];
            float2 t = g_twy[k2*SYv + n2];
            val += 2.0f*(s.x*t.x - s.y*t.y);
        }
        d[p] = val * (1.0f/(179.0f*15.0f));
    }
}

// ---------------- fused: h = gelu( mlp(g_t2) + c1(h) ) ----------------
__global__ void __launch_bounds__(256) k_fuse(
        const float* __restrict__ w1, const float* __restrict__ b1,
        const float* __restrict__ w2, const float* __restrict__ b2,
        const float* __restrict__ wr, const float* __restrict__ br){
    __shared__ float sw1[NC*NC], sw2[NC*NC], swr[NC*NC], sb1[NC], sb2[NC], sbr[NC];
    int t = threadIdx.x;
    for (int i = t; i < NC*NC; i += 256){ sw1[i] = w1[i]; sw2[i] = w2[i]; swr[i] = wr[i]; }
    if (t < NC){ sb1[t] = b1[t]; sb2[t] = b2[t]; sbr[t] = br[t]; }
    __syncthreads();
    int p = blockIdx.x*256 + t;
    if (p >= NP) return;
    size_t base = (size_t)blockIdx.y*NC*NP + p;
    float xin[NC], tm[NC];
    #pragma unroll
    for (int i = 0; i < NC; i++) xin[i] = g_t2[base + (size_t)i*NP];
    #pragma unroll
    for (int o = 0; o < NC; o++){
        float a = sb1[o];
        #pragma unroll
        for (int i = 0; i < NC; i++) a = fmaf(xin[i], sw1[o*NC+i], a);
        tm[o] = gelu_f(a);
    }
    float hin[NC];
    #pragma unroll
    for (int i = 0; i < NC; i++) hin[i] = g_h[base + (size_t)i*NP];
    #pragma unroll
    for (int o = 0; o < NC; o++){
        float a = sb2[o] + sbr[o];
        #pragma unroll
        for (int i = 0; i < NC; i++) a = fmaf(tm[i],  sw2[o*NC+i], a);
        #pragma unroll
        for (int i = 0; i < NC; i++) a = fmaf(hin[i], swr[o*NC+i], a);
        g_h[base + (size_t)o*NP] = gelu_f(a);
    }
}

// ---------------- spatial attention conv3x3 + relu + pool ----------------
__global__ void __launch_bounds__(256,1) k_conv(const float* __restrict__ cw,
                                                const float* __restrict__ cb){
    int b = blockIdx.x;
    __shared__ float sw[NC*NC*9];
    __shared__ float scb[NC];
    __shared__ float red[NC];
    int t = threadIdx.x;
    for (int i = t; i < NC*NC*9; i += 256) sw[i] = cw[i];
    if (t < NC){ scb[t] = cb[t]; red[t] = 0.f; }
    __syncthreads();
    const float* hb = g_h + (size_t)b*NC*NP;
    float acc[NC];
    #pragma unroll
    for (int o = 0; o < NC; o++) acc[o] = 0.f;
    const int PH = (NP+1)/2;   // 1343
    for (int p0 = t; p0 < PH; p0 += 256){
        int p1 = p0 + PH;
        bool has2 = (p1 < NP);
        float a0[NC], a1[NC];
        #pragma unroll
        for (int o = 0; o < NC; o++){ a0[o] = scb[o]; a1[o] = scb[o]; }
        int x0 = p0/SYv, y0 = p0%SYv;
        int x1 = p1/SYv, y1 = p1%SYv;
        for (int i = 0; i < NC; i++){
            const float* hi = hb + (size_t)i*NP;
            float v0[9], v1[9];
            #pragma unroll
            for (int dx = -1; dx <= 1; dx++)
            #pragma unroll
            for (int dy = -1; dy <= 1; dy++){
                int q = (dx+1)*3 + (dy+1);
                int xa = x0+dx, ya = y0+dy;
                v0[q] = (xa>=0 && xa<SXv && ya>=0 && ya<SYv) ? hi[xa*SYv+ya] : 0.f;
                int xb2 = x1+dx, yb2 = y1+dy;
                v1[q] = (has2 && xb2>=0 && xb2<SXv && yb2>=0 && yb2<SYv) ? hi[xb2*SYv+yb2] : 0.f;
            }
            #pragma unroll
            for (int o = 0; o < NC; o++){
                const float* w = &sw[(o*NC+i)*9];
                float s0 = 0.f, s1 = 0.f;
                #pragma unroll
                for (int q = 0; q < 9; q++){ s0 = fmaf(v0[q], w[q], s0); s1 = fmaf(v1[q], w[q], s1); }
                a0[o] += s0; a1[o] += s1;
            }
        }
        #pragma unroll
        for (int o = 0; o < NC; o++){
            acc[o] += fmaxf(a0[o], 0.f);
            if (has2) acc[o] += fmaxf(a1[o], 0.f);
        }
    }
    #pragma unroll
    for (int o = 0; o < NC; o++) atomicAdd(&red[o], acc[o]);
    __syncthreads();
    if (t < NC) g_ap[b*NC + t] = red[t] * (1.0f/NP);
}

__global__ void k_att(const float* __restrict__ fw, const float* __restrict__ fb){
    int b = blockIdx.x*blockDim.x + threadIdx.x;
    if (b < NB){
        float s = fb[0];
        #pragma unroll
        for (int c = 0; c < NC; c++) s = fmaf(g_ap[b*NC+c], fw[c], s);
        g_att[b] = 1.0f/(1.0f + expf(-s));
    }
}

// ---------------- generic split-K tiled SGEMM: C = A(256xK) * B(NxK)^T ----------------
template<int SEL, int SPLITK>
__global__ void __launch_bounds__(256) k_gemm(const float* __restrict__ Bmat, int N, int K){
    const float* A = (SEL == 0) ? g_h : g_C;
    int n0 = blockIdx.x*64, m0 = blockIdx.y*64, z = blockIdx.z;
    int ck = (K + SPLITK - 1)/SPLITK;
    int k0 = z*ck, kend = min(K, k0 + ck);
    __shared__ float As[64][17], Bs[64][17];
    float acc[4][4];
    #pragma unroll
    for (int mi = 0; mi < 4; mi++)
        #pragma unroll
        for (int ni = 0; ni < 4; ni++) acc[mi][ni] = 0.f;
    int tr = threadIdx.x >> 4, tc = threadIdx.x & 15;
    for (int kt = k0; kt < kend; kt += 16){
        #pragma unroll
        for (int l = 0; l < 4; l++){
            int i = threadIdx.x + l*256;
            int r = i >> 4, c = i & 15;
            int k = kt + c;
            As[r][c] = (k < kend) ? A[(size_t)(m0+r)*K + k] : 0.f;
            int j = n0 + r;
            Bs[r][c] = (k < kend && j < N) ? Bmat[(size_t)j*K + k] : 0.f;
        }
        __syncthreads();
        #pragma unroll
        for (int kk = 0; kk < 16; kk++){
            float a[4], bb[4];
            #pragma unroll
            for (int mi = 0; mi < 4; mi++) a[mi]  = As[tr*4+mi][kk];
            #pragma unroll
            for (int ni = 0; ni < 4; ni++) bb[ni] = Bs[tc*4+ni][kk];
            #pragma unroll
            for (int mi = 0; mi < 4; mi++)
                #pragma unroll
                for (int ni = 0; ni < 4; ni++) acc[mi][ni] = fmaf(a[mi], bb[ni], acc[mi][ni]);
        }
        __syncthreads();
    }
    #pragma unroll
    for (int mi = 0; mi < 4; mi++)
        #pragma unroll
        for (int ni = 0; ni < 4; ni++){
            int m = m0 + tr*4 + mi, n = n0 + tc*4 + ni;
            if (n < N) g_Cp[(size_t)z*NB*N + (size_t)m*N + n] = acc[mi][ni];
        }
}

__global__ void k_comb1(const float* __restrict__ b1){
    int i = blockIdx.x*256 + threadIdx.x;
    if (i >= NB*NH1) return;
    int b = i/NH1, j = i - b*NH1;
    float v = (g_Cp[i] + g_Cp[NB*NH1 + i]) * g_att[b] + b1[j];
    g_C[i] = (v > 0.f) ? v : 0.01f*v;
}

__global__ void k_comb2(const float* __restrict__ b2){
    int i = blockIdx.x*256 + threadIdx.x;
    if (i >= NB*NO) return;
    int j = i % NO;
    float v = b2[j];
    #pragma unroll
    for (int z = 0; z < 8; z++) v += g_Cp[(size_t)z*NB*NO + i];
    g_x1[i] = v;
}

__global__ void k_head(const float* __restrict__ x, const float* __restrict__ rw,
                       const float* __restrict__ rb, float* __restrict__ out){
    int b = blockIdx.x, t = threadIdx.x;   // 128 threads
    float x0 = (x[(size_t)b*SXv*(SYv+1) + t*(SYv+1) + SYv] - 400.0f)*0.01f;
    float v = g_x1[b*NO + t]*rw[2*t] + x0*rw[2*t+1];
    __shared__ float s[128];
    s[t] = v; __syncthreads();
    for (int o = 64; o > 0; o >>= 1){ if (t < o) s[t] += s[t+o]; __syncthreads(); }
    if (t == 0) out[b] = s[0] + rb[0];
}

// ---------------- launch ----------------
extern "C" void kernel_launch(void* const* d_in, const int* in_sizes, int n_in,
                              void* d_out, int out_size){
    const float* x      = (const float*)d_in[0];
    const float* p_w    = (const float*)d_in[1];
    const float* p_b    = (const float*)d_in[2];
    const float* sc0_w1 = (const float*)d_in[3];
    const float* sc0_w2 = (const float*)d_in[4];
    const float* sc1_w1 = (const float*)d_in[5];
    const float* sc1_w2 = (const float*)d_in[6];
    const float* mlp0_w1= (const float*)d_in[7];
    const float* mlp0_b1= (const float*)d_in[8];
    const float* mlp0_w2= (const float*)d_in[9];
    const float* mlp0_b2= (const float*)d_in[10];
    const float* mlp1_w1= (const float*)d_in[11];
    const float* mlp1_b1= (const float*)d_in[12];
    const float* mlp1_w2= (const float*)d_in[13];
    const float* mlp1_b2= (const float*)d_in[14];
    const float* w0_w   = (const float*)d_in[15];
    const float* w0_b   = (const float*)d_in[16];
    const float* w1_w   = (const float*)d_in[17];
    const float* w1_b   = (const float*)d_in[18];
    const float* sa_cw  = (const float*)d_in[19];
    const float* sa_cb  = (const float*)d_in[20];
    const float* sa_fw  = (const float*)d_in[21];
    const float* sa_fb  = (const float*)d_in[22];
    const float* o1_w1  = (const float*)d_in[23];
    const float* o1_b1  = (const float*)d_in[24];
    const float* o1_w2  = (const float*)d_in[25];
    const float* o1_b2  = (const float*)d_in[26];
    const float* reg2_w = (const float*)d_in[27];
    const float* reg2_b = (const float*)d_in[28];
    float* out = (float*)d_out;

    k_twiddle<<<6, 256>>>();
    k_build<<<NB*NC, 256>>>(x, p_w, p_b);

    // Fourier block 0
    k_inorm<<<NB*NC, 256>>>(0);
    k_fdft<<<NB*NC, 256>>>();
    k_mix<<<NB, 256>>>(sc0_w1, sc0_w2);
    k_idft<<<NB*NC, 256>>>();
    k_inorm<<<NB*NC, 256>>>(1);
    k_fuse<<<dim3((NP+255)/256, NB), 256>>>(mlp0_w1, mlp0_b1, mlp0_w2, mlp0_b2, w0_w, w0_b);

    // Fourier block 1
    k_inorm<<<NB*NC, 256>>>(0);
    k_fdft<<<NB*NC, 256>>>();
    k_mix<<<NB, 256>>>(sc1_w1, sc1_w2);
    k_idft<<<NB*NC, 256>>>();
    k_inorm<<<NB*NC, 256>>>(1);
    k_fuse<<<dim3((NP+255)/256, NB), 256>>>(mlp1_w1, mlp1_b1, mlp1_w2, mlp1_b2, w1_w, w1_b);

    // spatial attention
    k_conv<<<NB, 256>>>(sa_cw, sa_cb);
    k_att<<<1, 256>>>(sa_fw, sa_fb);

    // big GEMM (attention folded into epilogue) + head
    k_gemm<0,2><<<dim3((NH1+63)/64, 4, 2), 256>>>(o1_w1, NH1, KTOT);
    k_comb1<<<(NB*NH1+255)/256, 256>>>(o1_b1);
    k_gemm<1,8><<<dim3(2, 4, 8), 256>>>(o1_w2, NO, 2808);
    k_comb2<<<(NB*NO+255)/256, 256>>>(o1_b2);
    k_head<<<NB, 128>>>(x, reg2_w, reg2_b, out);
}

// round 4
// speedup vs baseline: 2.7006x; 2.7006x over previous
#include <cuda_runtime.h>
#include <math.h>
#include <stdint.h>

#define NB 256
#define NC 26
#define SXv 179
#define SYv 15
#define NP (SXv*SYv)          // 2685
#define MM 7
#define NMODE (14*MM)         // 98
#define KTOT (NC*NP)          // 69810
#define NH1 2808
#define NO 128
#define NCH32 2182            // ceil(69810/32)
#define SPLITK1 10

// ---------------- device scratch ----------------
__device__ float  g_h [NB*NC*NP];
__device__ float  g_t1[NB*NC*NP];
__device__ float  g_t2[NB*NC*NP];
__device__ float2 g_F [NB*NC*NMODE];
__device__ float2 g_G [NB*NC*NMODE];
__device__ float2 g_twx[8*SXv];
__device__ float2 g_twy[MM*SYv];
__device__ float  g_ap [NB*NC];
__device__ float  g_att[NB];
__device__ float  g_Cp [SPLITK1*NB*NH1];   // gemm1 partials; gemm2 reuses front (8*NB*NO)
__device__ float  g_C  [NB*NH1];
__device__ float  g_x1 [NB*NO];

__device__ __forceinline__ float gelu_f(float x){
    return 0.5f*x*(1.0f + erff(x*0.70710678118654752f));
}

__device__ __forceinline__ uint32_t smem_u32(const void* p){
    uint32_t a;
    asm("{ .reg .u64 t; cvta.to.shared.u64 t, %1; cvt.u32.u64 %0, t; }" : "=r"(a) : "l"(p));
    return a;
}

// ---------------- twiddle tables ----------------
__global__ void k_twiddle(){
    int i = blockIdx.x*blockDim.x + threadIdx.x;
    if (i < 8*SXv){
        int k = i/SXv, xx = i%SXv;
        float sn, cs;
        sincospif(2.0f*(float)(k*xx)/179.0f, &sn, &cs);
        g_twx[i] = make_float2(cs, sn);
    }
    if (i < MM*SYv){
        int k = i/SYv, y = i%SYv;
        float sn, cs;
        sincospif(2.0f*(float)(k*y)/15.0f, &sn, &cs);
        g_twy[i] = make_float2(cs, sn);
    }
}

// ---------------- lift ----------------
__global__ void k_build(const float* __restrict__ x,
                        const float* __restrict__ pw,
                        const float* __restrict__ pb){
    int bc = blockIdx.x;
    int b = bc / NC, w = bc % NC;
    float w0 = pw[w*3+0], w1 = pw[w*3+1], w2 = pw[w*3+2], bb = pb[w];
    const float* xb = x + (size_t)b*SXv*(SYv+1);
    float* out = g_h + (size_t)bc*NP;
    for (int p = threadIdx.x; p < NP; p += blockDim.x){
        int xi = p/SYv, yi = p%SYv;
        float u = xb[xi*(SYv+1) + yi];
        out[p] = u*w0 + ((float)xi*(1.0f/178.0f))*w1 + ((float)yi*(1.0f/14.0f))*w2 + bb;
    }
}

// ---------------- instance norm ----------------
__global__ void k_inorm(int mode){   // 0: g_h->g_t1, 1: g_t1->g_t2
    const float* s = (mode ? g_t1 : g_h) + (size_t)blockIdx.x*NP;
    float* d = (mode ? g_t2 : g_t1) + (size_t)blockIdx.x*NP;
    __shared__ float rs[256], rq[256];
    float sum = 0.f, sq = 0.f;
    for (int p = threadIdx.x; p < NP; p += 256){ float v = s[p]; sum += v; sq += v*v; }
    rs[threadIdx.x] = sum; rq[threadIdx.x] = sq;
    __syncthreads();
    for (int o = 128; o > 0; o >>= 1){
        if (threadIdx.x < o){ rs[threadIdx.x] += rs[threadIdx.x+o]; rq[threadIdx.x] += rq[threadIdx.x+o]; }
        __syncthreads();
    }
    float mu  = rs[0] * (1.0f/NP);
    float var = rq[0] * (1.0f/NP) - mu*mu;
    float inv = rsqrtf(var + 1e-5f);
    for (int p = threadIdx.x; p < NP; p += 256) d[p] = (s[p]-mu)*inv;
}

// ---------------- forward truncated DFT (g_t1 -> g_F) ----------------
__global__ void k_fdft(){
    int bc = blockIdx.x;
    __shared__ float  sp[NP];
    __shared__ float2 Ys[SXv*MM];
    const float* s = g_t1 + (size_t)bc*NP;
    for (int p = threadIdx.x; p < NP; p += 256) sp[p] = s[p];
    __syncthreads();
    for (int idx = threadIdx.x; idx < SXv*MM; idx += 256){
        int xx = idx/MM, k2 = idx%MM;
        float re = 0.f, im = 0.f;
        #pragma unroll
        for (int y = 0; y < SYv; y++){
            float2 t = g_twy[k2*SYv + y];
            float v = sp[xx*SYv + y];
            re = fmaf(v, t.x, re);
            im = fmaf(v, -t.y, im);
        }
        Ys[idx] = make_float2(re, im);
    }
    __syncthreads();
    for (int mode = threadIdx.x; mode < NMODE; mode += 256){
        int k1i = mode/MM, k2 = mode%MM;
        const float2* tw = g_twx + ((k1i < 7) ? k1i : (14-k1i))*SXv;
        float sgn = (k1i < 7) ? -1.f : 1.f;
        float re = 0.f, im = 0.f;
        #pragma unroll 4
        for (int xx = 0; xx < SXv; xx++){
            float2 u = tw[xx];
            float tc = u.x, ts = sgn*u.y;
            float2 y = Ys[xx*MM + k2];
            re += y.x*tc - y.y*ts;
            im += y.x*ts + y.y*tc;
        }
        g_F[(size_t)bc*NMODE + mode] = make_float2(re, im);
    }
}

// ---------------- complex channel mix (g_F -> g_G) ----------------
__global__ void k_mix(const float* __restrict__ w1, const float* __restrict__ w2){
    int b = blockIdx.x;
    __shared__ float2 Fs[NC*NMODE];
    for (int i = threadIdx.x; i < NC*NMODE; i += 256)
        Fs[i] = g_F[(size_t)b*NC*NMODE + i];
    __syncthreads();
    for (int oi = threadIdx.x; oi < NC*NMODE; oi += 256){
        int o = oi/NMODE, mode = oi%NMODE;
        int k1i = mode/MM, k2 = mode%MM;
        const float* wp;
        if (k1i < 7) wp = w1 + ((size_t)(o*MM + k1i)*MM + k2)*2;
        else         wp = w2 + ((size_t)(o*MM + (k1i-7))*MM + k2)*2;
        float re = 0.f, im = 0.f;
        #pragma unroll 2
        for (int i = 0; i < NC; i++){
            float2 f = Fs[i*NMODE + mode];
            float wr = wp[0], wi = wp[1];
            re += f.x*wr - f.y*wi;
            im += f.x*wi + f.y*wr;
            wp += NC*MM*MM*2;
        }
        g_G[(size_t)b*NC*NMODE + oi] = make_float2(re, im);
    }
}

// ---------------- inverse truncated DFT (g_G -> g_t1) ----------------
__global__ void k_idft(){
    int bc = blockIdx.x;
    __shared__ float2 Gs[NMODE];
    __shared__ float2 Ss[SXv*MM];
    for (int i = threadIdx.x; i < NMODE; i += 256)
        Gs[i] = g_G[(size_t)bc*NMODE + i];
    __syncthreads();
    for (int idx = threadIdx.x; idx < SXv*MM; idx += 256){
        int n1 = idx/MM, k2 = idx%MM;
        float re = 0.f, im = 0.f;
        #pragma unroll
        for (int k1i = 0; k1i < 14; k1i++){
            float2 g = Gs[k1i*MM + k2];
            float2 u = (k1i < 7) ? g_twx[k1i*SXv + n1] : g_twx[(14-k1i)*SXv + n1];
            float ts = (k1i < 7) ? u.y : -u.y;
            re += g.x*u.x - g.y*ts;
            im += g.x*ts + g.y*u.x;
        }
        Ss[idx] = make_float2(re, im);
    }
    __syncthreads();
    float* d = g_t1 + (size_t)bc*NP;
    for (int p = threadIdx.x; p < NP; p += 256){
        int n1 = p/SYv, n2 = p%SYv;
        float val = Ss[n1*MM].x;
        #pragma unroll
        for (int k2 = 1; k2 < MM; k2++){
            float2 s = Ss[n1*MM + k2];
            float2 t = g_twy[k2*SYv + n2];
            val += 2.0f*(s.x*t.x - s.y*t.y);
        }
        d[p] = val * (1.0f/(179.0f*15.0f));
    }
}

// ---------------- fused: h = gelu( mlp(g_t2) + c1(h) ) ----------------
__global__ void __launch_bounds__(256) k_fuse(
        const float* __restrict__ w1, const float* __restrict__ b1,
        const float* __restrict__ w2, const float* __restrict__ b2,
        const float* __restrict__ wr, const float* __restrict__ br){
    __shared__ float sw1[NC*NC], sw2[NC*NC], swr[NC*NC], sb1[NC], sb2[NC], sbr[NC];
    int t = threadIdx.x;
    for (int i = t; i < NC*NC; i += 256){ sw1[i] = w1[i]; sw2[i] = w2[i]; swr[i] = wr[i]; }
    if (t < NC){ sb1[t] = b1[t]; sb2[t] = b2[t]; sbr[t] = br[t]; }
    __syncthreads();
    int p = blockIdx.x*256 + t;
    if (p >= NP) return;
    size_t base = (size_t)blockIdx.y*NC*NP + p;
    float xin[NC], tm[NC];
    #pragma unroll
    for (int i = 0; i < NC; i++) xin[i] = g_t2[base + (size_t)i*NP];
    #pragma unroll
    for (int o = 0; o < NC; o++){
        float a = sb1[o];
        #pragma unroll
        for (int i = 0; i < NC; i++) a = fmaf(xin[i], sw1[o*NC+i], a);
        tm[o] = gelu_f(a);
    }
    float hin[NC];
    #pragma unroll
    for (int i = 0; i < NC; i++) hin[i] = g_h[base + (size_t)i*NP];
    #pragma unroll
    for (int o = 0; o < NC; o++){
        float a = sb2[o] + sbr[o];
        #pragma unroll
        for (int i = 0; i < NC; i++) a = fmaf(tm[i],  sw2[o*NC+i], a);
        #pragma unroll
        for (int i = 0; i < NC; i++) a = fmaf(hin[i], swr[o*NC+i], a);
        g_h[base + (size_t)o*NP] = gelu_f(a);
    }
}

// ---------------- spatial attention conv3x3 + relu + pool ----------------
__global__ void __launch_bounds__(256,1) k_conv(const float* __restrict__ cw,
                                                const float* __restrict__ cb){
    int b = blockIdx.x;
    __shared__ float sw[NC*NC*9];
    __shared__ float scb[NC];
    __shared__ float red[NC];
    int t = threadIdx.x;
    for (int i = t; i < NC*NC*9; i += 256) sw[i] = cw[i];
    if (t < NC){ scb[t] = cb[t]; red[t] = 0.f; }
    __syncthreads();
    const float* hb = g_h + (size_t)b*NC*NP;
    float acc[NC];
    #pragma unroll
    for (int o = 0; o < NC; o++) acc[o] = 0.f;
    const int PH = (NP+1)/2;   // 1343
    for (int p0 = t; p0 < PH; p0 += 256){
        int p1 = p0 + PH;
        bool has2 = (p1 < NP);
        float a0[NC], a1[NC];
        #pragma unroll
        for (int o = 0; o < NC; o++){ a0[o] = scb[o]; a1[o] = scb[o]; }
        int x0 = p0/SYv, y0 = p0%SYv;
        int x1 = p1/SYv, y1 = p1%SYv;
        for (int i = 0; i < NC; i++){
            const float* hi = hb + (size_t)i*NP;
            float v0[9], v1[9];
            #pragma unroll
            for (int dx = -1; dx <= 1; dx++)
            #pragma unroll
            for (int dy = -1; dy <= 1; dy++){
                int q = (dx+1)*3 + (dy+1);
                int xa = x0+dx, ya = y0+dy;
                v0[q] = (xa>=0 && xa<SXv && ya>=0 && ya<SYv) ? hi[xa*SYv+ya] : 0.f;
                int xb2 = x1+dx, yb2 = y1+dy;
                v1[q] = (has2 && xb2>=0 && xb2<SXv && yb2>=0 && yb2<SYv) ? hi[xb2*SYv+yb2] : 0.f;
            }
            #pragma unroll
            for (int o = 0; o < NC; o++){
                const float* w = &sw[(o*NC+i)*9];
                float s0 = 0.f, s1 = 0.f;
                #pragma unroll
                for (int q = 0; q < 9; q++){ s0 = fmaf(v0[q], w[q], s0); s1 = fmaf(v1[q], w[q], s1); }
                a0[o] += s0; a1[o] += s1;
            }
        }
        #pragma unroll
        for (int o = 0; o < NC; o++){
            acc[o] += fmaxf(a0[o], 0.f);
            if (has2) acc[o] += fmaxf(a1[o], 0.f);
        }
    }
    #pragma unroll
    for (int o = 0; o < NC; o++) atomicAdd(&red[o], acc[o]);
    __syncthreads();
    if (t < NC) g_ap[b*NC + t] = red[t] * (1.0f/NP);
}

__global__ void k_att(const float* __restrict__ fw, const float* __restrict__ fb){
    int b = blockIdx.x*blockDim.x + threadIdx.x;
    if (b < NB){
        float s = fb[0];
        #pragma unroll
        for (int c = 0; c < NC; c++) s = fmaf(g_ap[b*NC+c], fw[c], s);
        g_att[b] = 1.0f/(1.0f + expf(-s));
    }
}

// =====================================================================
// GEMM1 via mma.sync bf16 hi/lo split:  g_Cp[z] = partial A(256xK)*W(2808xK)^T
// CTA tile 128x128, 8 warps (2x4), warp tile 64x32, K-chunk 32, split-K 10.
// =====================================================================
#define G1_STRIDE 80          // bytes per smem row (32 bf16 + 8 pad)
#define G1_AH 0
#define G1_AL 10240
#define G1_BH 20480
#define G1_BL 30720
#define G1_STAGE 40960
#define G1_SMEM (2*G1_STAGE)

#define LDSM4(R, ADDR) \
    asm volatile("ldmatrix.sync.aligned.m8n8.x4.shared.b16 {%0,%1,%2,%3}, [%4];" \
        : "=r"((R)[0]), "=r"((R)[1]), "=r"((R)[2]), "=r"((R)[3]) : "r"(ADDR))

#define MMA16816(D, A, B0, B1) \
    asm volatile("mma.sync.aligned.m16n8k16.row.col.f32.bf16.bf16.f32 " \
        "{%0,%1,%2,%3}, {%4,%5,%6,%7}, {%8,%9}, {%0,%1,%2,%3};" \
        : "+f"((D)[0]), "+f"((D)[1]), "+f"((D)[2]), "+f"((D)[3]) \
        : "r"((A)[0]), "r"((A)[1]), "r"((A)[2]), "r"((A)[3]), "r"(B0), "r"(B1))

__device__ __forceinline__ void g1_cvt8(const float2* v, uint32_t* hi, uint32_t* lo){
    #pragma unroll
    for (int j = 0; j < 8; j++){
        float v0 = v[j].x, v1 = v[j].y;
        uint32_t h;
        asm("cvt.rn.bf16x2.f32 %0, %1, %2;" : "=r"(h) : "f"(v1), "f"(v0));
        float h0 = __uint_as_float(h << 16);
        float h1 = __uint_as_float(h & 0xFFFF0000u);
        float l0 = v0 - h0, l1 = v1 - h1;
        uint32_t l;
        asm("cvt.rn.bf16x2.f32 %0, %1, %2;" : "=r"(l) : "f"(l1), "f"(l0));
        hi[j] = h; lo[j] = l;
    }
}

__global__ void __launch_bounds__(256, 1) k_gemm1_mma(const float* __restrict__ W){
    extern __shared__ char smem[];
    uint32_t sbase = smem_u32(smem);
    int t = threadIdx.x;
    int wid = t >> 5, lane = t & 31;
    int n0 = blockIdx.x*128, m0 = blockIdx.y*128, z = blockIdx.z;
    int c0 = (z*NCH32)/SPLITK1, c1 = ((z+1)*NCH32)/SPLITK1;

    int m_w = (wid & 1)*64;          // warp M offset
    int n_w = (wid >> 1)*32;         // warp N offset

    int r = t >> 1, h = t & 1;       // load role: row r, k-half h
    const float* Ag = g_h + (size_t)(m0 + r)*KTOT;
    int brow = n0 + r;
    const float* Bg = W + (size_t)brow*KTOT;
    int bval = (brow < NH1);
    int kb0 = h*16;

    float acc[4][4][4];
    #pragma unroll
    for (int mi = 0; mi < 4; mi++)
        #pragma unroll
        for (int nj = 0; nj < 4; nj++)
            #pragma unroll
            for (int q = 0; q < 4; q++) acc[mi][nj][q] = 0.f;

    // ---- store chunk c into stage s helper (loads already in va/vb) ----
    char* myA = smem + (size_t)r*G1_STRIDE + h*32;
    // (stage/base added at use sites)

    // preload + store chunk c0 into stage 0
    {
        float2 va[8], vb[8];
        int kbase = c0*32 + kb0;
        #pragma unroll
        for (int j = 0; j < 8; j++){
            int kg = kbase + 2*j;
            va[j] = (kg < KTOT) ? *(const float2*)(Ag + kg) : make_float2(0.f, 0.f);
            vb[j] = (bval && kg < KTOT) ? *(const float2*)(Bg + kg) : make_float2(0.f, 0.f);
        }
        uint32_t ah[8], al[8], bh[8], bl[8];
        g1_cvt8(va, ah, al);
        g1_cvt8(vb, bh, bl);
        *(uint4*)(myA + G1_AH)      = *(uint4*)(ah);
        *(uint4*)(myA + G1_AH + 16) = *(uint4*)(ah+4);
        *(uint4*)(myA + G1_AL)      = *(uint4*)(al);
        *(uint4*)(myA + G1_AL + 16) = *(uint4*)(al+4);
        *(uint4*)(myA + G1_BH)      = *(uint4*)(bh);
        *(uint4*)(myA + G1_BH + 16) = *(uint4*)(bh+4);
        *(uint4*)(myA + G1_BL)      = *(uint4*)(bl);
        *(uint4*)(myA + G1_BL + 16) = *(uint4*)(bl+4);
    }
    __syncthreads();

    // ldmatrix lane addressing (constant per thread)
    uint32_t a_row = (uint32_t)(m_w + (lane & 15));
    uint32_t a_koff = ((lane >> 4) & 1)*16;
    uint32_t b_row = (uint32_t)(n_w + ((lane >> 4) & 1)*8 + (lane & 7));
    uint32_t b_koff = ((lane >> 3) & 1)*16;

    for (int c = c0; c < c1; c++){
        int s = (c - c0) & 1;
        uint32_t sb = sbase + (uint32_t)s*G1_STAGE;

        // prefetch next chunk (global) into registers
        float2 va[8], vb[8];
        bool more = (c + 1 < c1);
        if (more){
            int kbase = (c+1)*32 + kb0;
            #pragma unroll
            for (int j = 0; j < 8; j++){
                int kg = kbase + 2*j;
                va[j] = (kg < KTOT) ? *(const float2*)(Ag + kg) : make_float2(0.f, 0.f);
                vb[j] = (bval && kg < KTOT) ? *(const float2*)(Bg + kg) : make_float2(0.f, 0.f);
            }
        }

        // compute on stage s: two k16 steps
        #pragma unroll
        for (int ks = 0; ks < 2; ks++){
            uint32_t ksb = ks*32;
            uint32_t Ah[4][4], Al[4][4], Bh[2][4], Bl[2][4];
            #pragma unroll
            for (int mi = 0; mi < 4; mi++){
                uint32_t ad = sb + G1_AH + (a_row + mi*16)*G1_STRIDE + ksb + a_koff;
                LDSM4(Ah[mi], ad);
                LDSM4(Al[mi], ad + (G1_AL - G1_AH));
            }
            #pragma unroll
            for (int ni = 0; ni < 2; ni++){
                uint32_t bd = sb + G1_BH + (b_row + ni*16)*G1_STRIDE + ksb + b_koff;
                LDSM4(Bh[ni], bd);
                LDSM4(Bl[ni], bd + (G1_BL - G1_BH));
            }
            #pragma unroll
            for (int mi = 0; mi < 4; mi++)
                #pragma unroll
                for (int nj = 0; nj < 4; nj++){
                    uint32_t* BH = Bh[nj>>1] + 2*(nj&1);
                    uint32_t* BL = Bl[nj>>1] + 2*(nj&1);
                    MMA16816(acc[mi][nj], Ah[mi], BH[0], BH[1]);
                    MMA16816(acc[mi][nj], Ah[mi], BL[0], BL[1]);
                    MMA16816(acc[mi][nj], Al[mi], BH[0], BH[1]);
                }
        }

        // convert + store next chunk into other stage
        if (more){
            char* dst = smem + (s^1)*G1_STAGE + (size_t)r*G1_STRIDE + h*32;
            uint32_t ah[8], al[8], bh[8], bl[8];
            g1_cvt8(va, ah, al);
            g1_cvt8(vb, bh, bl);
            *(uint4*)(dst + G1_AH)      = *(uint4*)(ah);
            *(uint4*)(dst + G1_AH + 16) = *(uint4*)(ah+4);
            *(uint4*)(dst + G1_AL)      = *(uint4*)(al);
            *(uint4*)(dst + G1_AL + 16) = *(uint4*)(al+4);
            *(uint4*)(dst + G1_BH)      = *(uint4*)(bh);
            *(uint4*)(dst + G1_BH + 16) = *(uint4*)(bh+4);
            *(uint4*)(dst + G1_BL)      = *(uint4*)(bl);
            *(uint4*)(dst + G1_BL + 16) = *(uint4*)(bl+4);
        }
        __syncthreads();
    }

    // epilogue: write fp32 partials
    int g = lane >> 2, tig = lane & 3;
    #pragma unroll
    for (int mi = 0; mi < 4; mi++){
        int mrow = m0 + m_w + mi*16 + g;
        #pragma unroll
        for (int nj = 0; nj < 4; nj++){
            int ncol = n0 + n_w + nj*8 + 2*tig;
            if (ncol < NH1){
                float* d0 = g_Cp + ((size_t)z*NB + mrow)*NH1 + ncol;
                *(float2*)d0 = make_float2(acc[mi][nj][0], acc[mi][nj][1]);
                float* d1 = d0 + (size_t)8*NH1;
                *(float2*)d1 = make_float2(acc[mi][nj][2], acc[mi][nj][3]);
            }
        }
    }
}

__global__ void k_comb1(const float* __restrict__ b1){
    int i = blockIdx.x*256 + threadIdx.x;
    if (i >= NB*NH1) return;
    int b = i/NH1, j = i - b*NH1;
    float v = 0.f;
    #pragma unroll
    for (int z = 0; z < SPLITK1; z++) v += g_Cp[(size_t)z*NB*NH1 + i];
    v = v * g_att[b] + b1[j];
    g_C[i] = (v > 0.f) ? v : 0.01f*v;
}

// ---------------- small split-K tiled SGEMM for layer 2 ----------------
template<int SPLITK>
__global__ void __launch_bounds__(256) k_gemm(const float* __restrict__ Bmat, int N, int K){
    const float* A = g_C;
    int n0 = blockIdx.x*64, m0 = blockIdx.y*64, z = blockIdx.z;
    int ck = (K + SPLITK - 1)/SPLITK;
    int k0 = z*ck, kend = min(K, k0 + ck);
    __shared__ float As[64][17], Bs[64][17];
    float acc[4][4];
    #pragma unroll
    for (int mi = 0; mi < 4; mi++)
        #pragma unroll
        for (int ni = 0; ni < 4; ni++) acc[mi][ni] = 0.f;
    int tr = threadIdx.x >> 4, tc = threadIdx.x & 15;
    for (int kt = k0; kt < kend; kt += 16){
        #pragma unroll
        for (int l = 0; l < 4; l++){
            int i = threadIdx.x + l*256;
            int rr = i >> 4, cc = i & 15;
            int k = kt + cc;
            As[rr][cc] = (k < kend) ? A[(size_t)(m0+rr)*K + k] : 0.f;
            int j = n0 + rr;
            Bs[rr][cc] = (k < kend && j < N) ? Bmat[(size_t)j*K + k] : 0.f;
        }
        __syncthreads();
        #pragma unroll
        for (int kk = 0; kk < 16; kk++){
            float a[4], bb[4];
            #pragma unroll
            for (int mi = 0; mi < 4; mi++) a[mi]  = As[tr*4+mi][kk];
            #pragma unroll
            for (int ni = 0; ni < 4; ni++) bb[ni] = Bs[tc*4+ni][kk];
            #pragma unroll
            for (int mi = 0; mi < 4; mi++)
                #pragma unroll
                for (int ni = 0; ni < 4; ni++) acc[mi][ni] = fmaf(a[mi], bb[ni], acc[mi][ni]);
        }
        __syncthreads();
    }
    #pragma unroll
    for (int mi = 0; mi < 4; mi++)
        #pragma unroll
        for (int ni = 0; ni < 4; ni++){
            int m = m0 + tr*4 + mi, n = n0 + tc*4 + ni;
            if (n < N) g_Cp[(size_t)z*NB*N + (size_t)m*N + n] = acc[mi][ni];
        }
}

__global__ void k_comb2(const float* __restrict__ b2){
    int i = blockIdx.x*256 + threadIdx.x;
    if (i >= NB*NO) return;
    int j = i % NO;
    float v = b2[j];
    #pragma unroll
    for (int z = 0; z < 8; z++) v += g_Cp[(size_t)z*NB*NO + i];
    g_x1[i] = v;
}

__global__ void k_head(const float* __restrict__ x, const float* __restrict__ rw,
                       const float* __restrict__ rb, float* __restrict__ out){
    int b = blockIdx.x, t = threadIdx.x;   // 128 threads
    float x0 = (x[(size_t)b*SXv*(SYv+1) + t*(SYv+1) + SYv] - 400.0f)*0.01f;
    float v = g_x1[b*NO + t]*rw[2*t] + x0*rw[2*t+1];
    __shared__ float s[128];
    s[t] = v; __syncthreads();
    for (int o = 64; o > 0; o >>= 1){ if (t < o) s[t] += s[t+o]; __syncthreads(); }
    if (t == 0) out[b] = s[0] + rb[0];
}

// ---------------- launch ----------------
extern "C" void kernel_launch(void* const* d_in, const int* in_sizes, int n_in,
                              void* d_out, int out_size){
    const float* x      = (const float*)d_in[0];
    const float* p_w    = (const float*)d_in[1];
    const float* p_b    = (const float*)d_in[2];
    const float* sc0_w1 = (const float*)d_in[3];
    const float* sc0_w2 = (const float*)d_in[4];
    const float* sc1_w1 = (const float*)d_in[5];
    const float* sc1_w2 = (const float*)d_in[6];
    const float* mlp0_w1= (const float*)d_in[7];
    const float* mlp0_b1= (const float*)d_in[8];
    const float* mlp0_w2= (const float*)d_in[9];
    const float* mlp0_b2= (const float*)d_in[10];
    const float* mlp1_w1= (const float*)d_in[11];
    const float* mlp1_b1= (const float*)d_in[12];
    const float* mlp1_w2= (const float*)d_in[13];
    const float* mlp1_b2= (const float*)d_in[14];
    const float* w0_w   = (const float*)d_in[15];
    const float* w0_b   = (const float*)d_in[16];
    const float* w1_w   = (const float*)d_in[17];
    const float* w1_b   = (const float*)d_in[18];
    const float* sa_cw  = (const float*)d_in[19];
    const float* sa_cb  = (const float*)d_in[20];
    const float* sa_fw  = (const float*)d_in[21];
    const float* sa_fb  = (const float*)d_in[22];
    const float* o1_w1  = (const float*)d_in[23];
    const float* o1_b1  = (const float*)d_in[24];
    const float* o1_w2  = (const float*)d_in[25];
    const float* o1_b2  = (const float*)d_in[26];
    const float* reg2_w = (const float*)d_in[27];
    const float* reg2_b = (const float*)d_in[28];
    float* out = (float*)d_out;

    cudaFuncSetAttribute(k_gemm1_mma, cudaFuncAttributeMaxDynamicSharedMemorySize, G1_SMEM);

    k_twiddle<<<6, 256>>>();
    k_build<<<NB*NC, 256>>>(x, p_w, p_b);

    // Fourier block 0
    k_inorm<<<NB*NC, 256>>>(0);
    k_fdft<<<NB*NC, 256>>>();
    k_mix<<<NB, 256>>>(sc0_w1, sc0_w2);
    k_idft<<<NB*NC, 256>>>();
    k_inorm<<<NB*NC, 256>>>(1);
    k_fuse<<<dim3((NP+255)/256, NB), 256>>>(mlp0_w1, mlp0_b1, mlp0_w2, mlp0_b2, w0_w, w0_b);

    // Fourier block 1
    k_inorm<<<NB*NC, 256>>>(0);
    k_fdft<<<NB*NC, 256>>>();
    k_mix<<<NB, 256>>>(sc1_w1, sc1_w2);
    k_idft<<<NB*NC, 256>>>();
    k_inorm<<<NB*NC, 256>>>(1);
    k_fuse<<<dim3((NP+255)/256, NB), 256>>>(mlp1_w1, mlp1_b1, mlp1_w2, mlp1_b2, w1_w, w1_b);

    // spatial attention
    k_conv<<<NB, 256>>>(sa_cw, sa_cb);
    k_att<<<1, 256>>>(sa_fw, sa_fb);

    // big GEMM on tensor cores (mma.sync bf16 hi/lo split), attention folded into epilogue
    k_gemm1_mma<<<dim3(22, 2, SPLITK1), 256, G1_SMEM>>>(o1_w1);
    k_comb1<<<(NB*NH1+255)/256, 256>>>(o1_b1);
    k_gemm<8><<<dim3(2, 4, 8), 256>>>(o1_w2, NO, 2808);
    k_comb2<<<(NB*NO+255)/256, 256>>>(o1_b2);
    k_head<<<NB, 128>>>(x, reg2_w, reg2_b, out);
}

// round 5
// speedup vs baseline: 2.8501x; 1.0553x over previous
#include <cuda_runtime.h>
#include <math.h>
#include <stdint.h>

#define NB 256
#define NC 26
#define SXv 179
#define SYv 15
#define NP (SXv*SYv)          // 2685
#define MM 7
#define NMODE (14*MM)         // 98
#define KTOT (NC*NP)          // 69810
#define NH1 2808
#define NO 128
#define NCH32 2182            // ceil(69810/32)
#define SPLITK1 10

// ---------------- device scratch ----------------
__device__ float  g_h [NB*NC*NP];
__device__ float  g_t2[NB*NC*NP];
__device__ float2 g_F [NB*NC*NMODE];
__device__ float2 g_G [NB*NC*NMODE];
__device__ float2 g_twx[8*SXv];
__device__ float2 g_twy[MM*SYv];
__device__ float  g_ap [NB*NC];
__device__ float  g_att[NB];
__device__ float  g_Cp [SPLITK1*NB*NH1];   // gemm1 partials; gemm2 reuses front (8*NB*NO)
__device__ float  g_C  [NB*NH1];
__device__ float  g_x1 [NB*NO];

__device__ __forceinline__ float gelu_f(float x){
    return 0.5f*x*(1.0f + erff(x*0.70710678118654752f));
}

__device__ __forceinline__ uint32_t smem_u32(const void* p){
    uint32_t a;
    asm("{ .reg .u64 t; cvta.to.shared.u64 t, %1; cvt.u32.u64 %0, t; }" : "=r"(a) : "l"(p));
    return a;
}

// block-wide (256 thr) sum/sumsq reduction; result broadcast via shm[0],shm[1]
__device__ __forceinline__ void block_reduce2(float s, float q, float* shm,
                                              float& osum, float& osq){
    int t = threadIdx.x, lane = t & 31, wid = t >> 5;
    #pragma unroll
    for (int o = 16; o > 0; o >>= 1){
        s += __shfl_down_sync(0xFFFFFFFFu, s, o);
        q += __shfl_down_sync(0xFFFFFFFFu, q, o);
    }
    if (lane == 0){ shm[wid] = s; shm[8 + wid] = q; }
    __syncthreads();
    if (t == 0){
        float ss = 0.f, qq = 0.f;
        #pragma unroll
        for (int i = 0; i < 8; i++){ ss += shm[i]; qq += shm[8 + i]; }
        shm[16] = ss; shm[17] = qq;
    }
    __syncthreads();
    osum = shm[16]; osq = shm[17];
}

// ---------------- twiddle tables ----------------
__global__ void k_twiddle(){
    int i = blockIdx.x*blockDim.x + threadIdx.x;
    if (i < 8*SXv){
        int k = i/SXv, xx = i%SXv;
        float sn, cs;
        sincospif(2.0f*(float)(k*xx)/179.0f, &sn, &cs);
        g_twx[i] = make_float2(cs, sn);
    }
    if (i < MM*SYv){
        int k = i/SYv, y = i%SYv;
        float sn, cs;
        sincospif(2.0f*(float)(k*y)/15.0f, &sn, &cs);
        g_twy[i] = make_float2(cs, sn);
    }
}

// ---------------- fused lift + instance-norm + forward truncated DFT ----------------
// first=1: compute h from x (and store g_h);  first=0: read g_h.
// Normalization applied only to DFT input (residual keeps raw h) — matches reference.
__global__ void __launch_bounds__(256) k_fdft(const float* __restrict__ x,
                                              const float* __restrict__ pw,
                                              const float* __restrict__ pb,
                                              int first){
    int bc = blockIdx.x;
    __shared__ float  sp[NP];
    __shared__ float2 Ys[SXv*MM];
    __shared__ float2 Pp[2*NMODE];
    __shared__ float  red[18];
    int t = threadIdx.x;

    float s = 0.f, q = 0.f;
    if (first){
        int b = bc / NC, w = bc % NC;
        float w0 = pw[w*3+0], w1 = pw[w*3+1], w2 = pw[w*3+2], bb = pb[w];
        const float* xb = x + (size_t)b*SXv*(SYv+1);
        float* outp = g_h + (size_t)bc*NP;
        for (int p = t; p < NP; p += 256){
            int xi = p/SYv, yi = p%SYv;
            float u = xb[xi*(SYv+1) + yi];
            float v = u*w0 + ((float)xi*(1.0f/178.0f))*w1 + ((float)yi*(1.0f/14.0f))*w2 + bb;
            outp[p] = v;
            sp[p] = v;
            s += v; q += v*v;
        }
    } else {
        const float* src = g_h + (size_t)bc*NP;
        for (int p = t; p < NP; p += 256){
            float v = src[p];
            sp[p] = v;
            s += v; q += v*v;
        }
    }
    __syncthreads();
    float sum, sq;
    block_reduce2(s, q, red, sum, sq);
    float mu  = sum * (1.0f/NP);
    float var = sq * (1.0f/NP) - mu*mu;
    float inv = rsqrtf(var + 1e-5f);
    for (int p = t; p < NP; p += 256) sp[p] = (sp[p] - mu)*inv;
    __syncthreads();

    // y-DFT
    for (int idx = t; idx < SXv*MM; idx += 256){
        int xx = idx/MM, k2 = idx%MM;
        float re = 0.f, im = 0.f;
        #pragma unroll
        for (int y = 0; y < SYv; y++){
            float2 tw = g_twy[k2*SYv + y];
            float v = sp[xx*SYv + y];
            re = fmaf(v, tw.x, re);
            im = fmaf(v, -tw.y, im);
        }
        Ys[idx] = make_float2(re, im);
    }
    __syncthreads();

    // x-DFT: 2 threads per mode (x split at 90)
    if (t < 2*NMODE){
        int mode = t >> 1, half = t & 1;
        int k1i = mode/MM, k2 = mode%MM;
        const float2* tw = g_twx + ((k1i < 7) ? k1i : (14-k1i))*SXv;
        float sgn = (k1i < 7) ? -1.f : 1.f;
        int xa = half ? 90 : 0, xbnd = half ? SXv : 90;
        float re = 0.f, im = 0.f;
        #pragma unroll 3
        for (int xx = xa; xx < xbnd; xx++){
            float2 u = tw[xx];
            float tc = u.x, ts = sgn*u.y;
            float2 y = Ys[xx*MM + k2];
            re += y.x*tc - y.y*ts;
            im += y.x*ts + y.y*tc;
        }
        Pp[t] = make_float2(re, im);
    }
    __syncthreads();
    if (t < NMODE){
        float2 a = Pp[2*t], b2 = Pp[2*t+1];
        g_F[(size_t)bc*NMODE + t] = make_float2(a.x + b2.x, a.y + b2.y);
    }
}

// ---------------- complex channel mix (g_F -> g_G) ----------------
__global__ void k_mix(const float* __restrict__ w1, const float* __restrict__ w2){
    int b = blockIdx.x;
    __shared__ float2 Fs[NC*NMODE];
    for (int i = threadIdx.x; i < NC*NMODE; i += 256)
        Fs[i] = g_F[(size_t)b*NC*NMODE + i];
    __syncthreads();
    for (int oi = threadIdx.x; oi < NC*NMODE; oi += 256){
        int o = oi/NMODE, mode = oi%NMODE;
        int k1i = mode/MM, k2 = mode%MM;
        const float* wp;
        if (k1i < 7) wp = w1 + ((size_t)(o*MM + k1i)*MM + k2)*2;
        else         wp = w2 + ((size_t)(o*MM + (k1i-7))*MM + k2)*2;
        float re = 0.f, im = 0.f;
        #pragma unroll 2
        for (int i = 0; i < NC; i++){
            float2 f = Fs[i*NMODE + mode];
            float wr = wp[0], wi = wp[1];
            re += f.x*wr - f.y*wi;
            im += f.x*wi + f.y*wr;
            wp += NC*MM*MM*2;
        }
        g_G[(size_t)b*NC*NMODE + oi] = make_float2(re, im);
    }
}

// ---------------- fused inverse truncated DFT + instance norm (g_G -> g_t2) ----------------
__global__ void __launch_bounds__(256) k_idft(){
    int bc = blockIdx.x;
    __shared__ float2 Gs[NMODE];
    __shared__ float2 Ss[SXv*MM];
    __shared__ float  pl[NP];
    __shared__ float  red[18];
    int t = threadIdx.x;
    for (int i = t; i < NMODE; i += 256)
        Gs[i] = g_G[(size_t)bc*NMODE + i];
    __syncthreads();
    for (int idx = t; idx < SXv*MM; idx += 256){
        int n1 = idx/MM, k2 = idx%MM;
        float re = 0.f, im = 0.f;
        #pragma unroll
        for (int k1i = 0; k1i < 14; k1i++){
            float2 g = Gs[k1i*MM + k2];
            float2 u = (k1i < 7) ? g_twx[k1i*SXv + n1] : g_twx[(14-k1i)*SXv + n1];
            float ts = (k1i < 7) ? u.y : -u.y;
            re += g.x*u.x - g.y*ts;
            im += g.x*ts + g.y*u.x;
        }
        Ss[idx] = make_float2(re, im);
    }
    __syncthreads();
    float s = 0.f, q = 0.f;
    for (int p = t; p < NP; p += 256){
        int n1 = p/SYv, n2 = p%SYv;
        float val = Ss[n1*MM].x;
        #pragma unroll
        for (int k2 = 1; k2 < MM; k2++){
            float2 sv = Ss[n1*MM + k2];
            float2 tw = g_twy[k2*SYv + n2];
            val += 2.0f*(sv.x*tw.x - sv.y*tw.y);
        }
        val *= (1.0f/(179.0f*15.0f));
        pl[p] = val;
        s += val; q += val*val;
    }
    __syncthreads();
    float sum, sq;
    block_reduce2(s, q, red, sum, sq);
    float mu  = sum * (1.0f/NP);
    float var = sq * (1.0f/NP) - mu*mu;
    float inv = rsqrtf(var + 1e-5f);
    float* d = g_t2 + (size_t)bc*NP;
    for (int p = t; p < NP; p += 256) d[p] = (pl[p] - mu)*inv;
}

// ---------------- fused: h = gelu( mlp(g_t2) + c1(h) ) ----------------
__global__ void __launch_bounds__(256) k_fuse(
        const float* __restrict__ w1, const float* __restrict__ b1,
        const float* __restrict__ w2, const float* __restrict__ b2,
        const float* __restrict__ wr, const float* __restrict__ br){
    __shared__ float sw1[NC*NC], sw2[NC*NC], swr[NC*NC], sb1[NC], sb2[NC], sbr[NC];
    int t = threadIdx.x;
    for (int i = t; i < NC*NC; i += 256){ sw1[i] = w1[i]; sw2[i] = w2[i]; swr[i] = wr[i]; }
    if (t < NC){ sb1[t] = b1[t]; sb2[t] = b2[t]; sbr[t] = br[t]; }
    __syncthreads();
    int p = blockIdx.x*256 + t;
    if (p >= NP) return;
    size_t base = (size_t)blockIdx.y*NC*NP + p;
    float xin[NC], tm[NC];
    #pragma unroll
    for (int i = 0; i < NC; i++) xin[i] = g_t2[base + (size_t)i*NP];
    #pragma unroll
    for (int o = 0; o < NC; o++){
        float a = sb1[o];
        #pragma unroll
        for (int i = 0; i < NC; i++) a = fmaf(xin[i], sw1[o*NC+i], a);
        tm[o] = gelu_f(a);
    }
    float hin[NC];
    #pragma unroll
    for (int i = 0; i < NC; i++) hin[i] = g_h[base + (size_t)i*NP];
    #pragma unroll
    for (int o = 0; o < NC; o++){
        float a = sb2[o] + sbr[o];
        #pragma unroll
        for (int i = 0; i < NC; i++) a = fmaf(tm[i],  sw2[o*NC+i], a);
        #pragma unroll
        for (int i = 0; i < NC; i++) a = fmaf(hin[i], swr[o*NC+i], a);
        g_h[base + (size_t)o*NP] = gelu_f(a);
    }
}

// ---------------- spatial attention conv3x3 + relu + pool ----------------
__global__ void __launch_bounds__(256,1) k_conv(const float* __restrict__ cw,
                                                const float* __restrict__ cb){
    int b = blockIdx.x;
    __shared__ float sw[NC*NC*9];
    __shared__ float scb[NC];
    __shared__ float red[NC];
    int t = threadIdx.x;
    for (int i = t; i < NC*NC*9; i += 256) sw[i] = cw[i];
    if (t < NC){ scb[t] = cb[t]; red[t] = 0.f; }
    __syncthreads();
    const float* hb = g_h + (size_t)b*NC*NP;
    float acc[NC];
    #pragma unroll
    for (int o = 0; o < NC; o++) acc[o] = 0.f;
    const int PH = (NP+1)/2;   // 1343
    for (int p0 = t; p0 < PH; p0 += 256){
        int p1 = p0 + PH;
        bool has2 = (p1 < NP);
        float a0[NC], a1[NC];
        #pragma unroll
        for (int o = 0; o < NC; o++){ a0[o] = scb[o]; a1[o] = scb[o]; }
        int x0 = p0/SYv, y0 = p0%SYv;
        int x1 = p1/SYv, y1 = p1%SYv;
        for (int i = 0; i < NC; i++){
            const float* hi = hb + (size_t)i*NP;
            float v0[9], v1[9];
            #pragma unroll
            for (int dx = -1; dx <= 1; dx++)
            #pragma unroll
            for (int dy = -1; dy <= 1; dy++){
                int qd = (dx+1)*3 + (dy+1);
                int xa = x0+dx, ya = y0+dy;
                v0[qd] = (xa>=0 && xa<SXv && ya>=0 && ya<SYv) ? hi[xa*SYv+ya] : 0.f;
                int xb2 = x1+dx, yb2 = y1+dy;
                v1[qd] = (has2 && xb2>=0 && xb2<SXv && yb2>=0 && yb2<SYv) ? hi[xb2*SYv+yb2] : 0.f;
            }
            #pragma unroll
            for (int o = 0; o < NC; o++){
                const float* w = &sw[(o*NC+i)*9];
                float s0 = 0.f, s1 = 0.f;
                #pragma unroll
                for (int qd = 0; qd < 9; qd++){ s0 = fmaf(v0[qd], w[qd], s0); s1 = fmaf(v1[qd], w[qd], s1); }
                a0[o] += s0; a1[o] += s1;
            }
        }
        #pragma unroll
        for (int o = 0; o < NC; o++){
            acc[o] += fmaxf(a0[o], 0.f);
            if (has2) acc[o] += fmaxf(a1[o], 0.f);
        }
    }
    #pragma unroll
    for (int o = 0; o < NC; o++) atomicAdd(&red[o], acc[o]);
    __syncthreads();
    if (t < NC) g_ap[b*NC + t] = red[t] * (1.0f/NP);
}

__global__ void k_att(const float* __restrict__ fw, const float* __restrict__ fb){
    int b = blockIdx.x*blockDim.x + threadIdx.x;
    if (b < NB){
        float s = fb[0];
        #pragma unroll
        for (int c = 0; c < NC; c++) s = fmaf(g_ap[b*NC+c], fw[c], s);
        g_att[b] = 1.0f/(1.0f + expf(-s));
    }
}

// =====================================================================
// GEMM1 via mma.sync bf16 hi/lo split:  g_Cp[z] = partial A(256xK)*W(2808xK)^T
// CTA tile 128x128, 8 warps (2x4), warp tile 64x32, K-chunk 32, split-K 10.
// =====================================================================
#define G1_STRIDE 80          // bytes per smem row (32 bf16 + 8 pad)
#define G1_AH 0
#define G1_AL 10240
#define G1_BH 20480
#define G1_BL 30720
#define G1_STAGE 40960
#define G1_SMEM (2*G1_STAGE)

#define LDSM4(R, ADDR) \
    asm volatile("ldmatrix.sync.aligned.m8n8.x4.shared.b16 {%0,%1,%2,%3}, [%4];" \
        : "=r"((R)[0]), "=r"((R)[1]), "=r"((R)[2]), "=r"((R)[3]) : "r"(ADDR))

#define MMA16816(D, A, B0, B1) \
    asm volatile("mma.sync.aligned.m16n8k16.row.col.f32.bf16.bf16.f32 " \
        "{%0,%1,%2,%3}, {%4,%5,%6,%7}, {%8,%9}, {%0,%1,%2,%3};" \
        : "+f"((D)[0]), "+f"((D)[1]), "+f"((D)[2]), "+f"((D)[3]) \
        : "r"((A)[0]), "r"((A)[1]), "r"((A)[2]), "r"((A)[3]), "r"(B0), "r"(B1))

__device__ __forceinline__ void g1_cvt8(const float2* v, uint32_t* hi, uint32_t* lo){
    #pragma unroll
    for (int j = 0; j < 8; j++){
        float v0 = v[j].x, v1 = v[j].y;
        uint32_t h;
        asm("cvt.rn.bf16x2.f32 %0, %1, %2;" : "=r"(h) : "f"(v1), "f"(v0));
        float h0 = __uint_as_float(h << 16);
        float h1 = __uint_as_float(h & 0xFFFF0000u);
        float l0 = v0 - h0, l1 = v1 - h1;
        uint32_t l;
        asm("cvt.rn.bf16x2.f32 %0, %1, %2;" : "=r"(l) : "f"(l1), "f"(l0));
        hi[j] = h; lo[j] = l;
    }
}

__global__ void __launch_bounds__(256, 1) k_gemm1_mma(const float* __restrict__ W){
    extern __shared__ char smem[];
    uint32_t sbase = smem_u32(smem);
    int t = threadIdx.x;
    int wid = t >> 5, lane = t & 31;
    int n0 = blockIdx.x*128, m0 = blockIdx.y*128, z = blockIdx.z;
    int c0 = (z*NCH32)/SPLITK1, c1 = ((z+1)*NCH32)/SPLITK1;

    int m_w = (wid & 1)*64;          // warp M offset
    int n_w = (wid >> 1)*32;         // warp N offset

    int r = t >> 1, h = t & 1;       // load role: row r, k-half h
    const float* Ag = g_h + (size_t)(m0 + r)*KTOT;
    int brow = n0 + r;
    const float* Bg = W + (size_t)brow*KTOT;
    int bval = (brow < NH1);
    int kb0 = h*16;

    float acc[4][4][4];
    #pragma unroll
    for (int mi = 0; mi < 4; mi++)
        #pragma unroll
        for (int nj = 0; nj < 4; nj++)
            #pragma unroll
            for (int q = 0; q < 4; q++) acc[mi][nj][q] = 0.f;

    char* myA = smem + (size_t)r*G1_STRIDE + h*32;

    // preload + store chunk c0 into stage 0
    {
        float2 va[8], vb[8];
        int kbase = c0*32 + kb0;
        #pragma unroll
        for (int j = 0; j < 8; j++){
            int kg = kbase + 2*j;
            va[j] = (kg < KTOT) ? *(const float2*)(Ag + kg) : make_float2(0.f, 0.f);
            vb[j] = (bval && kg < KTOT) ? *(const float2*)(Bg + kg) : make_float2(0.f, 0.f);
        }
        uint32_t ah[8], al[8], bh[8], bl[8];
        g1_cvt8(va, ah, al);
        g1_cvt8(vb, bh, bl);
        *(uint4*)(myA + G1_AH)      = *(uint4*)(ah);
        *(uint4*)(myA + G1_AH + 16) = *(uint4*)(ah+4);
        *(uint4*)(myA + G1_AL)      = *(uint4*)(al);
        *(uint4*)(myA + G1_AL + 16) = *(uint4*)(al+4);
        *(uint4*)(myA + G1_BH)      = *(uint4*)(bh);
        *(uint4*)(myA + G1_BH + 16) = *(uint4*)(bh+4);
        *(uint4*)(myA + G1_BL)      = *(uint4*)(bl);
        *(uint4*)(myA + G1_BL + 16) = *(uint4*)(bl+4);
    }
    __syncthreads();

    uint32_t a_row = (uint32_t)(m_w + (lane & 15));
    uint32_t a_koff = ((lane >> 4) & 1)*16;
    uint32_t b_row = (uint32_t)(n_w + ((lane >> 4) & 1)*8 + (lane & 7));
    uint32_t b_koff = ((lane >> 3) & 1)*16;

    for (int c = c0; c < c1; c++){
        int s = (c - c0) & 1;
        uint32_t sb = sbase + (uint32_t)s*G1_STAGE;

        float2 va[8], vb[8];
        bool more = (c + 1 < c1);
        if (more){
            int kbase = (c+1)*32 + kb0;
            #pragma unroll
            for (int j = 0; j < 8; j++){
                int kg = kbase + 2*j;
                va[j] = (kg < KTOT) ? *(const float2*)(Ag + kg) : make_float2(0.f, 0.f);
                vb[j] = (bval && kg < KTOT) ? *(const float2*)(Bg + kg) : make_float2(0.f, 0.f);
            }
        }

        #pragma unroll
        for (int ks = 0; ks < 2; ks++){
            uint32_t ksb = ks*32;
            uint32_t Ah[4][4], Al[4][4], Bh[2][4], Bl[2][4];
            #pragma unroll
            for (int mi = 0; mi < 4; mi++){
                uint32_t ad = sb + G1_AH + (a_row + mi*16)*G1_STRIDE + ksb + a_koff;
                LDSM4(Ah[mi], ad);
                LDSM4(Al[mi], ad + (G1_AL - G1_AH));
            }
            #pragma unroll
            for (int ni = 0; ni < 2; ni++){
                uint32_t bd = sb + G1_BH + (b_row + ni*16)*G1_STRIDE + ksb + b_koff;
                LDSM4(Bh[ni], bd);
                LDSM4(Bl[ni], bd + (G1_BL - G1_BH));
            }
            #pragma unroll
            for (int mi = 0; mi < 4; mi++)
                #pragma unroll
                for (int nj = 0; nj < 4; nj++){
                    uint32_t* BH = Bh[nj>>1] + 2*(nj&1);
                    uint32_t* BL = Bl[nj>>1] + 2*(nj&1);
                    MMA16816(acc[mi][nj], Ah[mi], BH[0], BH[1]);
                    MMA16816(acc[mi][nj], Ah[mi], BL[0], BL[1]);
                    MMA16816(acc[mi][nj], Al[mi], BH[0], BH[1]);
                }
        }

        if (more){
            char* dst = smem + (s^1)*G1_STAGE + (size_t)r*G1_STRIDE + h*32;
            uint32_t ah[8], al[8], bh[8], bl[8];
            g1_cvt8(va, ah, al);
            g1_cvt8(vb, bh, bl);
            *(uint4*)(dst + G1_AH)      = *(uint4*)(ah);
            *(uint4*)(dst + G1_AH + 16) = *(uint4*)(ah+4);
            *(uint4*)(dst + G1_AL)      = *(uint4*)(al);
            *(uint4*)(dst + G1_AL + 16) = *(uint4*)(al+4);
            *(uint4*)(dst + G1_BH)      = *(uint4*)(bh);
            *(uint4*)(dst + G1_BH + 16) = *(uint4*)(bh+4);
            *(uint4*)(dst + G1_BL)      = *(uint4*)(bl);
            *(uint4*)(dst + G1_BL + 16) = *(uint4*)(bl+4);
        }
        __syncthreads();
    }

    int g = lane >> 2, tig = lane & 3;
    #pragma unroll
    for (int mi = 0; mi < 4; mi++){
        int mrow = m0 + m_w + mi*16 + g;
        #pragma unroll
        for (int nj = 0; nj < 4; nj++){
            int ncol = n0 + n_w + nj*8 + 2*tig;
            if (ncol < NH1){
                float* d0 = g_Cp + ((size_t)z*NB + mrow)*NH1 + ncol;
                *(float2*)d0 = make_float2(acc[mi][nj][0], acc[mi][nj][1]);
                float* d1 = d0 + (size_t)8*NH1;
                *(float2*)d1 = make_float2(acc[mi][nj][2], acc[mi][nj][3]);
            }
        }
    }
}

__global__ void k_comb1(const float* __restrict__ b1){
    int i = blockIdx.x*256 + threadIdx.x;
    if (i >= NB*NH1) return;
    int b = i/NH1, j = i - b*NH1;
    float v = 0.f;
    #pragma unroll
    for (int z = 0; z < SPLITK1; z++) v += g_Cp[(size_t)z*NB*NH1 + i];
    v = v * g_att[b] + b1[j];
    g_C[i] = (v > 0.f) ? v : 0.01f*v;
}

// ---------------- small split-K tiled SGEMM for layer 2 ----------------
template<int SPLITK>
__global__ void __launch_bounds__(256) k_gemm(const float* __restrict__ Bmat, int N, int K){
    const float* A = g_C;
    int n0 = blockIdx.x*64, m0 = blockIdx.y*64, z = blockIdx.z;
    int ck = (K + SPLITK - 1)/SPLITK;
    int k0 = z*ck, kend = min(K, k0 + ck);
    __shared__ float As[64][17], Bs[64][17];
    float acc[4][4];
    #pragma unroll
    for (int mi = 0; mi < 4; mi++)
        #pragma unroll
        for (int ni = 0; ni < 4; ni++) acc[mi][ni] = 0.f;
    int tr = threadIdx.x >> 4, tc = threadIdx.x & 15;
    for (int kt = k0; kt < kend; kt += 16){
        #pragma unroll
        for (int l = 0; l < 4; l++){
            int i = threadIdx.x + l*256;
            int rr = i >> 4, cc = i & 15;
            int k = kt + cc;
            As[rr][cc] = (k < kend) ? A[(size_t)(m0+rr)*K + k] : 0.f;
            int j = n0 + rr;
            Bs[rr][cc] = (k < kend && j < N) ? Bmat[(size_t)j*K + k] : 0.f;
        }
        __syncthreads();
        #pragma unroll
        for (int kk = 0; kk < 16; kk++){
            float a[4], bb[4];
            #pragma unroll
            for (int mi = 0; mi < 4; mi++) a[mi]  = As[tr*4+mi][kk];
            #pragma unroll
            for (int ni = 0; ni < 4; ni++) bb[ni] = Bs[tc*4+ni][kk];
            #pragma unroll
            for (int mi = 0; mi < 4; mi++)
                #pragma unroll
                for (int ni = 0; ni < 4; ni++) acc[mi][ni] = fmaf(a[mi], bb[ni], acc[mi][ni]);
        }
        __syncthreads();
    }
    #pragma unroll
    for (int mi = 0; mi < 4; mi++)
        #pragma unroll
        for (int ni = 0; ni < 4; ni++){
            int m = m0 + tr*4 + mi, n = n0 + tc*4 + ni;
            if (n < N) g_Cp[(size_t)z*NB*N + (size_t)m*N + n] = acc[mi][ni];
        }
}

__global__ void k_comb2(const float* __restrict__ b2){
    int i = blockIdx.x*256 + threadIdx.x;
    if (i >= NB*NO) return;
    int j = i % NO;
    float v = b2[j];
    #pragma unroll
    for (int z = 0; z < 8; z++) v += g_Cp[(size_t)z*NB*NO + i];
    g_x1[i] = v;
}

__global__ void k_head(const float* __restrict__ x, const float* __restrict__ rw,
                       const float* __restrict__ rb, float* __restrict__ out){
    int b = blockIdx.x, t = threadIdx.x;   // 128 threads
    float x0 = (x[(size_t)b*SXv*(SYv+1) + t*(SYv+1) + SYv] - 400.0f)*0.01f;
    float v = g_x1[b*NO + t]*rw[2*t] + x0*rw[2*t+1];
    __shared__ float s[128];
    s[t] = v; __syncthreads();
    for (int o = 64; o > 0; o >>= 1){ if (t < o) s[t] += s[t+o]; __syncthreads(); }
    if (t == 0) out[b] = s[0] + rb[0];
}

// ---------------- launch ----------------
extern "C" void kernel_launch(void* const* d_in, const int* in_sizes, int n_in,
                              void* d_out, int out_size){
    const float* x      = (const float*)d_in[0];
    const float* p_w    = (const float*)d_in[1];
    const float* p_b    = (const float*)d_in[2];
    const float* sc0_w1 = (const float*)d_in[3];
    const float* sc0_w2 = (const float*)d_in[4];
    const float* sc1_w1 = (const float*)d_in[5];
    const float* sc1_w2 = (const float*)d_in[6];
    const float* mlp0_w1= (const float*)d_in[7];
    const float* mlp0_b1= (const float*)d_in[8];
    const float* mlp0_w2= (const float*)d_in[9];
    const float* mlp0_b2= (const float*)d_in[10];
    const float* mlp1_w1= (const float*)d_in[11];
    const float* mlp1_b1= (const float*)d_in[12];
    const float* mlp1_w2= (const float*)d_in[13];
    const float* mlp1_b2= (const float*)d_in[14];
    const float* w0_w   = (const float*)d_in[15];
    const float* w0_b   = (const float*)d_in[16];
    const float* w1_w   = (const float*)d_in[17];
    const float* w1_b   = (const float*)d_in[18];
    const float* sa_cw  = (const float*)d_in[19];
    const float* sa_cb  = (const float*)d_in[20];
    const float* sa_fw  = (const float*)d_in[21];
    const float* sa_fb  = (const float*)d_in[22];
    const float* o1_w1  = (const float*)d_in[23];
    const float* o1_b1  = (const float*)d_in[24];
    const float* o1_w2  = (const float*)d_in[25];
    const float* o1_b2  = (const float*)d_in[26];
    const float* reg2_w = (const float*)d_in[27];
    const float* reg2_b = (const float*)d_in[28];
    float* out = (float*)d_out;

    cudaFuncSetAttribute(k_gemm1_mma, cudaFuncAttributeMaxDynamicSharedMemorySize, G1_SMEM);

    k_twiddle<<<6, 256>>>();

    // Fourier block 0 (lift + inorm fused into fdft; inorm fused into idft)
    k_fdft<<<NB*NC, 256>>>(x, p_w, p_b, 1);
    k_mix<<<NB, 256>>>(sc0_w1, sc0_w2);
    k_idft<<<NB*NC, 256>>>();
    k_fuse<<<dim3((NP+255)/256, NB), 256>>>(mlp0_w1, mlp0_b1, mlp0_w2, mlp0_b2, w0_w, w0_b);

    // Fourier block 1
    k_fdft<<<NB*NC, 256>>>(x, p_w, p_b, 0);
    k_mix<<<NB, 256>>>(sc1_w1, sc1_w2);
    k_idft<<<NB*NC, 256>>>();
    k_fuse<<<dim3((NP+255)/256, NB), 256>>>(mlp1_w1, mlp1_b1, mlp1_w2, mlp1_b2, w1_w, w1_b);

    // spatial attention
    k_conv<<<NB, 256>>>(sa_cw, sa_cb);
    k_att<<<1, 256>>>(sa_fw, sa_fb);

    // big GEMM on tensor cores (mma.sync bf16 hi/lo split), attention folded into epilogue
    k_gemm1_mma<<<dim3(22, 2, SPLITK1), 256, G1_SMEM>>>(o1_w1);
    k_comb1<<<(NB*NH1+255)/256, 256>>>(o1_b1);
    k_gemm<8><<<dim3(2, 4, 8), 256>>>(o1_w2, NO, 2808);
    k_comb2<<<(NB*NO+255)/256, 256>>>(o1_b2);
    k_head<<<NB, 128>>>(x, reg2_w, reg2_b, out);
}

// round 6
// speedup vs baseline: 3.2294x; 1.1331x over previous
#include <cuda_runtime.h>
#include <math.h>
#include <stdint.h>

#define NB 256
#define NC 26
#define SXv 179
#define SYv 15
#define NP (SXv*SYv)          // 2685
#define MM 7
#define NMODE (14*MM)         // 98
#define KTOT (NC*NP)          // 69810
#define NH1 2808
#define NO 128
#define NCH32 2182            // ceil(69810/32)
#define SPLITK1 10

// ---------------- device scratch ----------------
__device__ float  g_h [NB*NC*NP];
__device__ float  g_t2[NB*NC*NP];
__device__ float2 g_F [NB*NC*NMODE];
__device__ float2 g_G [NB*NC*NMODE];
__device__ float2 g_twx[8*SXv];
__device__ float2 g_twy[MM*SYv];
__device__ float  g_ap [NB*NC];
__device__ float  g_att[NB];
__device__ float  g_Cp [SPLITK1*NB*NH1];
__device__ float  g_C  [NB*NH1];
__device__ float  g_x1 [NB*NO];

__device__ __forceinline__ float gelu_f(float x){
    return 0.5f*x*(1.0f + erff(x*0.70710678118654752f));
}

__device__ __forceinline__ uint32_t smem_u32(const void* p){
    uint32_t a;
    asm("{ .reg .u64 t; cvta.to.shared.u64 t, %1; cvt.u32.u64 %0, t; }" : "=r"(a) : "l"(p));
    return a;
}

__device__ __forceinline__ void block_reduce2(float s, float q, float* shm,
                                              float& osum, float& osq){
    int t = threadIdx.x, lane = t & 31, wid = t >> 5;
    #pragma unroll
    for (int o = 16; o > 0; o >>= 1){
        s += __shfl_down_sync(0xFFFFFFFFu, s, o);
        q += __shfl_down_sync(0xFFFFFFFFu, q, o);
    }
    if (lane == 0){ shm[wid] = s; shm[8 + wid] = q; }
    __syncthreads();
    if (t == 0){
        float ss = 0.f, qq = 0.f;
        #pragma unroll
        for (int i = 0; i < 8; i++){ ss += shm[i]; qq += shm[8 + i]; }
        shm[16] = ss; shm[17] = qq;
    }
    __syncthreads();
    osum = shm[16]; osq = shm[17];
}

// ---------------- twiddle tables + g_ap zero ----------------
__global__ void k_twiddle(){
    int i = blockIdx.x*blockDim.x + threadIdx.x;
    if (i < 8*SXv){
        int k = i/SXv, xx = i%SXv;
        float sn, cs;
        sincospif(2.0f*(float)(k*xx)/179.0f, &sn, &cs);
        g_twx[i] = make_float2(cs, sn);
    }
    if (i < MM*SYv){
        int k = i/SYv, y = i%SYv;
        float sn, cs;
        sincospif(2.0f*(float)(k*y)/15.0f, &sn, &cs);
        g_twy[i] = make_float2(cs, sn);
    }
    if (i < NB*NC) g_ap[i] = 0.f;
}

// ---------------- fused lift + instance-norm + forward truncated DFT ----------------
__global__ void __launch_bounds__(256) k_fdft(const float* __restrict__ x,
                                              const float* __restrict__ pw,
                                              const float* __restrict__ pb,
                                              int first){
    int bc = blockIdx.x;
    __shared__ float  sp[NP];
    __shared__ float2 Ys[SXv*MM];
    __shared__ float2 Pp[2*NMODE];
    __shared__ float  red[18];
    int t = threadIdx.x;

    float s = 0.f, q = 0.f;
    if (first){
        int b = bc / NC, w = bc % NC;
        float w0 = pw[w*3+0], w1 = pw[w*3+1], w2 = pw[w*3+2], bb = pb[w];
        const float* xb = x + (size_t)b*SXv*(SYv+1);
        float* outp = g_h + (size_t)bc*NP;
        for (int p = t; p < NP; p += 256){
            int xi = p/SYv, yi = p%SYv;
            float u = xb[xi*(SYv+1) + yi];
            float v = u*w0 + ((float)xi*(1.0f/178.0f))*w1 + ((float)yi*(1.0f/14.0f))*w2 + bb;
            outp[p] = v;
            sp[p] = v;
            s += v; q += v*v;
        }
    } else {
        const float* src = g_h + (size_t)bc*NP;
        for (int p = t; p < NP; p += 256){
            float v = src[p];
            sp[p] = v;
            s += v; q += v*v;
        }
    }
    __syncthreads();
    float sum, sq;
    block_reduce2(s, q, red, sum, sq);
    float mu  = sum * (1.0f/NP);
    float var = sq * (1.0f/NP) - mu*mu;
    float inv = rsqrtf(var + 1e-5f);
    for (int p = t; p < NP; p += 256) sp[p] = (sp[p] - mu)*inv;
    __syncthreads();

    for (int idx = t; idx < SXv*MM; idx += 256){
        int xx = idx/MM, k2 = idx%MM;
        float re = 0.f, im = 0.f;
        #pragma unroll
        for (int y = 0; y < SYv; y++){
            float2 tw = g_twy[k2*SYv + y];
            float v = sp[xx*SYv + y];
            re = fmaf(v, tw.x, re);
            im = fmaf(v, -tw.y, im);
        }
        Ys[idx] = make_float2(re, im);
    }
    __syncthreads();

    if (t < 2*NMODE){
        int mode = t >> 1, half = t & 1;
        int k1i = mode/MM, k2 = mode%MM;
        const float2* tw = g_twx + ((k1i < 7) ? k1i : (14-k1i))*SXv;
        float sgn = (k1i < 7) ? -1.f : 1.f;
        int xa = half ? 90 : 0, xbnd = half ? SXv : 90;
        float re = 0.f, im = 0.f;
        #pragma unroll 3
        for (int xx = xa; xx < xbnd; xx++){
            float2 u = tw[xx];
            float tc = u.x, ts = sgn*u.y;
            float2 y = Ys[xx*MM + k2];
            re += y.x*tc - y.y*ts;
            im += y.x*ts + y.y*tc;
        }
        Pp[t] = make_float2(re, im);
    }
    __syncthreads();
    if (t < NMODE){
        float2 a = Pp[2*t], b2 = Pp[2*t+1];
        g_F[(size_t)bc*NMODE + t] = make_float2(a.x + b2.x, a.y + b2.y);
    }
}

// ---------------- complex channel mix (g_F -> g_G) ----------------
__global__ void k_mix(const float* __restrict__ w1, const float* __restrict__ w2){
    int b = blockIdx.x;
    __shared__ float2 Fs[NC*NMODE];
    for (int i = threadIdx.x; i < NC*NMODE; i += 256)
        Fs[i] = g_F[(size_t)b*NC*NMODE + i];
    __syncthreads();
    for (int oi = threadIdx.x; oi < NC*NMODE; oi += 256){
        int o = oi/NMODE, mode = oi%NMODE;
        int k1i = mode/MM, k2 = mode%MM;
        const float* wp;
        if (k1i < 7) wp = w1 + ((size_t)(o*MM + k1i)*MM + k2)*2;
        else         wp = w2 + ((size_t)(o*MM + (k1i-7))*MM + k2)*2;
        float re = 0.f, im = 0.f;
        #pragma unroll 2
        for (int i = 0; i < NC; i++){
            float2 f = Fs[i*NMODE + mode];
            float wr = wp[0], wi = wp[1];
            re += f.x*wr - f.y*wi;
            im += f.x*wi + f.y*wr;
            wp += NC*MM*MM*2;
        }
        g_G[(size_t)b*NC*NMODE + oi] = make_float2(re, im);
    }
}

// ---------------- fused inverse truncated DFT + instance norm (g_G -> g_t2) ----------------
__global__ void __launch_bounds__(256) k_idft(){
    int bc = blockIdx.x;
    __shared__ float2 Gs[NMODE];
    __shared__ float2 Ss[SXv*MM];
    __shared__ float  pl[NP];
    __shared__ float  red[18];
    int t = threadIdx.x;
    for (int i = t; i < NMODE; i += 256)
        Gs[i] = g_G[(size_t)bc*NMODE + i];
    __syncthreads();
    for (int idx = t; idx < SXv*MM; idx += 256){
        int n1 = idx/MM, k2 = idx%MM;
        float re = 0.f, im = 0.f;
        #pragma unroll
        for (int k1i = 0; k1i < 14; k1i++){
            float2 g = Gs[k1i*MM + k2];
            float2 u = (k1i < 7) ? g_twx[k1i*SXv + n1] : g_twx[(14-k1i)*SXv + n1];
            float ts = (k1i < 7) ? u.y : -u.y;
            re += g.x*u.x - g.y*ts;
            im += g.x*ts + g.y*u.x;
        }
        Ss[idx] = make_float2(re, im);
    }
    __syncthreads();
    float s = 0.f, q = 0.f;
    for (int p = t; p < NP; p += 256){
        int n1 = p/SYv, n2 = p%SYv;
        float val = Ss[n1*MM].x;
        #pragma unroll
        for (int k2 = 1; k2 < MM; k2++){
            float2 sv = Ss[n1*MM + k2];
            float2 tw = g_twy[k2*SYv + n2];
            val += 2.0f*(sv.x*tw.x - sv.y*tw.y);
        }
        val *= (1.0f/(179.0f*15.0f));
        pl[p] = val;
        s += val; q += val*val;
    }
    __syncthreads();
    float sum, sq;
    block_reduce2(s, q, red, sum, sq);
    float mu  = sum * (1.0f/NP);
    float var = sq * (1.0f/NP) - mu*mu;
    float inv = rsqrtf(var + 1e-5f);
    float* d = g_t2 + (size_t)bc*NP;
    for (int p = t; p < NP; p += 256) d[p] = (pl[p] - mu)*inv;
}

// ---------------- fused: h = gelu( mlp(g_t2) + c1(h) ) ----------------
__global__ void __launch_bounds__(256) k_fuse(
        const float* __restrict__ w1, const float* __restrict__ b1,
        const float* __restrict__ w2, const float* __restrict__ b2,
        const float* __restrict__ wr, const float* __restrict__ br){
    __shared__ float sw1[NC*NC], sw2[NC*NC], swr[NC*NC], sb1[NC], sb2[NC], sbr[NC];
    int t = threadIdx.x;
    for (int i = t; i < NC*NC; i += 256){ sw1[i] = w1[i]; sw2[i] = w2[i]; swr[i] = wr[i]; }
    if (t < NC){ sb1[t] = b1[t]; sb2[t] = b2[t]; sbr[t] = br[t]; }
    __syncthreads();
    int p = blockIdx.x*256 + t;
    if (p >= NP) return;
    size_t base = (size_t)blockIdx.y*NC*NP + p;
    float xin[NC], tm[NC];
    #pragma unroll
    for (int i = 0; i < NC; i++) xin[i] = g_t2[base + (size_t)i*NP];
    #pragma unroll
    for (int o = 0; o < NC; o++){
        float a = sb1[o];
        #pragma unroll
        for (int i = 0; i < NC; i++) a = fmaf(xin[i], sw1[o*NC+i], a);
        tm[o] = gelu_f(a);
    }
    float hin[NC];
    #pragma unroll
    for (int i = 0; i < NC; i++) hin[i] = g_h[base + (size_t)i*NP];
    #pragma unroll
    for (int o = 0; o < NC; o++){
        float a = sb2[o] + sbr[o];
        #pragma unroll
        for (int i = 0; i < NC; i++) a = fmaf(tm[i],  sw2[o*NC+i], a);
        #pragma unroll
        for (int i = 0; i < NC; i++) a = fmaf(hin[i], swr[o*NC+i], a);
        g_h[base + (size_t)o*NP] = gelu_f(a);
    }
}

// =====================================================================
// Tensor-core conv3x3 + relu + pooling (fused).
// Padded plane: rows of PADY=17 (y=0,16 are zero). 9 taps = row offsets.
// X single bf16 (positionally-independent rounding, pooled away);
// W hi/lo split (correlated rounding must stay small).
// Pool fused: relu -> shuffle reduce -> shared red -> global atomics to g_ap.
// =====================================================================
#define PADY 17
#define PPTOT (SXv*PADY)      // 3043
#define CTM 128
#define NTILE 24              // ceil(3043/128)
#define CROWS (CTM + 36)      // 164
#define XSTR 80               // smem row stride bytes (64 data + 16 pad)
#define CV_XS 0
#define CV_WH (CROWS*XSTR)                 // 13120
#define CV_WL (CV_WH + 9*32*XSTR)          // +23040 = 36160
#define CV_RED (CV_WL + 9*32*XSTR)         // 59200
#define CV_SMEM (CV_RED + 128)             // 59328

#define LDSM4(R, ADDR) \
    asm volatile("ldmatrix.sync.aligned.m8n8.x4.shared.b16 {%0,%1,%2,%3}, [%4];" \
        : "=r"((R)[0]), "=r"((R)[1]), "=r"((R)[2]), "=r"((R)[3]) : "r"(ADDR))

#define MMA16816(D, A, B0, B1) \
    asm volatile("mma.sync.aligned.m16n8k16.row.col.f32.bf16.bf16.f32 " \
        "{%0,%1,%2,%3}, {%4,%5,%6,%7}, {%8,%9}, {%0,%1,%2,%3};" \
        : "+f"((D)[0]), "+f"((D)[1]), "+f"((D)[2]), "+f"((D)[3]) \
        : "r"((A)[0]), "r"((A)[1]), "r"((A)[2]), "r"((A)[3]), "r"(B0), "r"(B1))

__global__ void __launch_bounds__(256) k_conv_tc(const float* __restrict__ cw,
                                                 const float* __restrict__ cb){
    extern __shared__ char smem[];
    uint32_t sbase = smem_u32(smem);
    float* red = (float*)(smem + CV_RED);
    int t = threadIdx.x;
    int wid = t >> 5, lane = t & 31;
    int tile = blockIdx.x, b = blockIdx.y;
    int p0 = tile*CTM;

    if (t < 32) red[t] = 0.f;

    // load W hi/lo: ws[q][o][i]
    for (int idx = t; idx < 9*32*32; idx += 256){
        int qd = idx >> 10, rem = idx & 1023;
        int o = rem >> 5, i = rem & 31;
        float v = (o < NC && i < NC) ? cw[(o*NC + i)*9 + qd] : 0.f;
        uint32_t hb = __float_as_uint(v) & 0xFFFF0000u;
        // round-to-nearest bf16 for hi
        uint32_t hr;
        asm("cvt.rn.bf16x2.f32 %0, %1, %2;" : "=r"(hr) : "f"(0.f), "f"(v));
        hb = hr << 16;
        float hi_f = __uint_as_float(hb);
        float lo_f = v - hi_f;
        uint32_t lr;
        asm("cvt.rn.bf16x2.f32 %0, %1, %2;" : "=r"(lr) : "f"(0.f), "f"(lo_f));
        uint32_t off = (uint32_t)qd*32*XSTR + (uint32_t)o*XSTR + (uint32_t)i*2;
        *(uint16_t*)(smem + CV_WH + off) = (uint16_t)(hr & 0xFFFF);
        *(uint16_t*)(smem + CV_WL + off) = (uint16_t)(lr & 0xFFFF);
    }

    // load X tile: rows [p0-18, p0+146) x 32 channels, bf16
    const float* hb_ptr = g_h + (size_t)b*NC*NP;
    for (int idx = t; idx < CROWS*32; idx += 256){
        int c = idx / CROWS, row = idx % CROWS;
        int pp = p0 - 18 + row;
        float v = 0.f;
        if (c < NC && pp >= 0 && pp < PPTOT){
            int xx = pp / PADY, yy = pp % PADY;
            if (yy >= 1 && yy <= 15) v = hb_ptr[(size_t)c*NP + xx*SYv + (yy-1)];
        }
        uint32_t r2;
        asm("cvt.rn.bf16x2.f32 %0, %1, %2;" : "=r"(r2) : "f"(0.f), "f"(v));
        *(uint16_t*)(smem + CV_XS + (uint32_t)row*XSTR + (uint32_t)c*2) = (uint16_t)(r2 & 0xFFFF);
    }
    __syncthreads();

    float acc[4][4];
    #pragma unroll
    for (int nj = 0; nj < 4; nj++)
        #pragma unroll
        for (int qd = 0; qd < 4; qd++) acc[nj][qd] = 0.f;

    uint32_t a_base = sbase + CV_XS + (uint32_t)(18 + wid*16 + (lane & 15))*XSTR + ((lane >> 4)*16);
    uint32_t b_row = (uint32_t)(((lane >> 4) & 1)*8 + (lane & 7));
    uint32_t b_koff = ((lane >> 3) & 1)*16;

    #pragma unroll
    for (int qd = 0; qd < 9; qd++){
        int off = (qd/3 - 1)*PADY + (qd%3 - 1);
        uint32_t wq = (uint32_t)qd*32*XSTR;
        #pragma unroll
        for (int ks = 0; ks < 2; ks++){
            uint32_t Af[4], Bh[2][4], Bl[2][4];
            LDSM4(Af, a_base + off*XSTR + ks*32);
            #pragma unroll
            for (int ni = 0; ni < 2; ni++){
                uint32_t bd = sbase + CV_WH + wq + (b_row + ni*16)*XSTR + ks*32 + b_koff;
                LDSM4(Bh[ni], bd);
                LDSM4(Bl[ni], bd + (CV_WL - CV_WH));
            }
            #pragma unroll
            for (int nj = 0; nj < 4; nj++){
                uint32_t* BH = Bh[nj>>1] + 2*(nj&1);
                uint32_t* BL = Bl[nj>>1] + 2*(nj&1);
                MMA16816(acc[nj], Af, BH[0], BH[1]);
                MMA16816(acc[nj], Af, BL[0], BL[1]);
            }
        }
    }

    // epilogue: bias + relu + validity mask + pool
    int g = lane >> 2, tig = lane & 3;
    int r0 = p0 + wid*16 + g;
    int r1 = r0 + 8;
    int y0 = r0 % PADY, y1 = r1 % PADY;
    bool v0 = (r0 < PPTOT) && (y0 >= 1) && (y0 <= 15);
    bool v1 = (r1 < PPTOT) && (y1 >= 1) && (y1 <= 15);

    #pragma unroll
    for (int nj = 0; nj < 4; nj++){
        int c0 = nj*8 + 2*tig, c1 = c0 + 1;
        float bc0 = (c0 < NC) ? cb[c0] : 0.f;
        float bc1 = (c1 < NC) ? cb[c1] : 0.f;
        float s0 = v0 ? fmaxf(acc[nj][0] + bc0, 0.f) : 0.f;
        float s1 = v0 ? fmaxf(acc[nj][1] + bc1, 0.f) : 0.f;
        float s2 = v1 ? fmaxf(acc[nj][2] + bc0, 0.f) : 0.f;
        float s3 = v1 ? fmaxf(acc[nj][3] + bc1, 0.f) : 0.f;
        float t0 = s0 + s2, t1 = s1 + s3;
        #pragma unroll
        for (int o = 16; o >= 4; o >>= 1){
            t0 += __shfl_down_sync(0xFFFFFFFFu, t0, o);
            t1 += __shfl_down_sync(0xFFFFFFFFu, t1, o);
        }
        if (lane < 4){
            if (c0 < NC) atomicAdd(&red[c0], t0);
            if (c1 < NC) atomicAdd(&red[c1], t1);
        }
    }
    __syncthreads();
    if (t < NC) atomicAdd(&g_ap[b*NC + t], red[t]);
}

__global__ void k_att(const float* __restrict__ fw, const float* __restrict__ fb){
    int b = blockIdx.x*blockDim.x + threadIdx.x;
    if (b < NB){
        float s = fb[0];
        #pragma unroll
        for (int c = 0; c < NC; c++) s = fmaf(g_ap[b*NC+c]*(1.0f/NP), fw[c], s);
        g_att[b] = 1.0f/(1.0f + expf(-s));
    }
}

// =====================================================================
// GEMM1 via mma.sync bf16 hi/lo split (unchanged from R4 win)
// =====================================================================
#define G1_STRIDE 80
#define G1_AH 0
#define G1_AL 10240
#define G1_BH 20480
#define G1_BL 30720
#define G1_STAGE 40960
#define G1_SMEM (2*G1_STAGE)

__device__ __forceinline__ void g1_cvt8(const float2* v, uint32_t* hi, uint32_t* lo){
    #pragma unroll
    for (int j = 0; j < 8; j++){
        float v0 = v[j].x, v1 = v[j].y;
        uint32_t h;
        asm("cvt.rn.bf16x2.f32 %0, %1, %2;" : "=r"(h) : "f"(v1), "f"(v0));
        float h0 = __uint_as_float(h << 16);
        float h1 = __uint_as_float(h & 0xFFFF0000u);
        float l0 = v0 - h0, l1 = v1 - h1;
        uint32_t l;
        asm("cvt.rn.bf16x2.f32 %0, %1, %2;" : "=r"(l) : "f"(l1), "f"(l0));
        hi[j] = h; lo[j] = l;
    }
}

__global__ void __launch_bounds__(256, 1) k_gemm1_mma(const float* __restrict__ W){
    extern __shared__ char smem[];
    uint32_t sbase = smem_u32(smem);
    int t = threadIdx.x;
    int wid = t >> 5, lane = t & 31;
    int n0 = blockIdx.x*128, m0 = blockIdx.y*128, z = blockIdx.z;
    int c0 = (z*NCH32)/SPLITK1, c1 = ((z+1)*NCH32)/SPLITK1;

    int m_w = (wid & 1)*64;
    int n_w = (wid >> 1)*32;

    int r = t >> 1, h = t & 1;
    const float* Ag = g_h + (size_t)(m0 + r)*KTOT;
    int brow = n0 + r;
    const float* Bg = W + (size_t)brow*KTOT;
    int bval = (brow < NH1);
    int kb0 = h*16;

    float acc[4][4][4];
    #pragma unroll
    for (int mi = 0; mi < 4; mi++)
        #pragma unroll
        for (int nj = 0; nj < 4; nj++)
            #pragma unroll
            for (int q = 0; q < 4; q++) acc[mi][nj][q] = 0.f;

    char* myA = smem + (size_t)r*G1_STRIDE + h*32;

    {
        float2 va[8], vb[8];
        int kbase = c0*32 + kb0;
        #pragma unroll
        for (int j = 0; j < 8; j++){
            int kg = kbase + 2*j;
            va[j] = (kg < KTOT) ? *(const float2*)(Ag + kg) : make_float2(0.f, 0.f);
            vb[j] = (bval && kg < KTOT) ? *(const float2*)(Bg + kg) : make_float2(0.f, 0.f);
        }
        uint32_t ah[8], al[8], bh[8], bl[8];
        g1_cvt8(va, ah, al);
        g1_cvt8(vb, bh, bl);
        *(uint4*)(myA + G1_AH)      = *(uint4*)(ah);
        *(uint4*)(myA + G1_AH + 16) = *(uint4*)(ah+4);
        *(uint4*)(myA + G1_AL)      = *(uint4*)(al);
        *(uint4*)(myA + G1_AL + 16) = *(uint4*)(al+4);
        *(uint4*)(myA + G1_BH)      = *(uint4*)(bh);
        *(uint4*)(myA + G1_BH + 16) = *(uint4*)(bh+4);
        *(uint4*)(myA + G1_BL)      = *(uint4*)(bl);
        *(uint4*)(myA + G1_BL + 16) = *(uint4*)(bl+4);
    }
    __syncthreads();

    uint32_t a_row = (uint32_t)(m_w + (lane & 15));
    uint32_t a_koff = ((lane >> 4) & 1)*16;
    uint32_t b_row = (uint32_t)(n_w + ((lane >> 4) & 1)*8 + (lane & 7));
    uint32_t b_koff = ((lane >> 3) & 1)*16;

    for (int c = c0; c < c1; c++){
        int s = (c - c0) & 1;
        uint32_t sb = sbase + (uint32_t)s*G1_STAGE;

        float2 va[8], vb[8];
        bool more = (c + 1 < c1);
        if (more){
            int kbase = (c+1)*32 + kb0;
            #pragma unroll
            for (int j = 0; j < 8; j++){
                int kg = kbase + 2*j;
                va[j] = (kg < KTOT) ? *(const float2*)(Ag + kg) : make_float2(0.f, 0.f);
                vb[j] = (bval && kg < KTOT) ? *(const float2*)(Bg + kg) : make_float2(0.f, 0.f);
            }
        }

        #pragma unroll
        for (int ks = 0; ks < 2; ks++){
            uint32_t ksb = ks*32;
            uint32_t Ah[4][4], Al[4][4], Bh[2][4], Bl[2][4];
            #pragma unroll
            for (int mi = 0; mi < 4; mi++){
                uint32_t ad = sb + G1_AH + (a_row + mi*16)*G1_STRIDE + ksb + a_koff;
                LDSM4(Ah[mi], ad);
                LDSM4(Al[mi], ad + (G1_AL - G1_AH));
            }
            #pragma unroll
            for (int ni = 0; ni < 2; ni++){
                uint32_t bd = sb + G1_BH + (b_row + ni*16)*G1_STRIDE + ksb + b_koff;
                LDSM4(Bh[ni], bd);
                LDSM4(Bl[ni], bd + (G1_BL - G1_BH));
            }
            #pragma unroll
            for (int mi = 0; mi < 4; mi++)
                #pragma unroll
                for (int nj = 0; nj < 4; nj++){
                    uint32_t* BH = Bh[nj>>1] + 2*(nj&1);
                    uint32_t* BL = Bl[nj>>1] + 2*(nj&1);
                    MMA16816(acc[mi][nj], Ah[mi], BH[0], BH[1]);
                    MMA16816(acc[mi][nj], Ah[mi], BL[0], BL[1]);
                    MMA16816(acc[mi][nj], Al[mi], BH[0], BH[1]);
                }
        }

        if (more){
            char* dst = smem + (s^1)*G1_STAGE + (size_t)r*G1_STRIDE + h*32;
            uint32_t ah[8], al[8], bh[8], bl[8];
            g1_cvt8(va, ah, al);
            g1_cvt8(vb, bh, bl);
            *(uint4*)(dst + G1_AH)      = *(uint4*)(ah);
            *(uint4*)(dst + G1_AH + 16) = *(uint4*)(ah+4);
            *(uint4*)(dst + G1_AL)      = *(uint4*)(al);
            *(uint4*)(dst + G1_AL + 16) = *(uint4*)(al+4);
            *(uint4*)(dst + G1_BH)      = *(uint4*)(bh);
            *(uint4*)(dst + G1_BH + 16) = *(uint4*)(bh+4);
            *(uint4*)(dst + G1_BL)      = *(uint4*)(bl);
            *(uint4*)(dst + G1_BL + 16) = *(uint4*)(bl+4);
        }
        __syncthreads();
    }

    int g = lane >> 2, tig = lane & 3;
    #pragma unroll
    for (int mi = 0; mi < 4; mi++){
        int mrow = m0 + m_w + mi*16 + g;
        #pragma unroll
        for (int nj = 0; nj < 4; nj++){
            int ncol = n0 + n_w + nj*8 + 2*tig;
            if (ncol < NH1){
                float* d0 = g_Cp + ((size_t)z*NB + mrow)*NH1 + ncol;
                *(float2*)d0 = make_float2(acc[mi][nj][0], acc[mi][nj][1]);
                float* d1 = d0 + (size_t)8*NH1;
                *(float2*)d1 = make_float2(acc[mi][nj][2], acc[mi][nj][3]);
            }
        }
    }
}

__global__ void k_comb1(const float* __restrict__ b1){
    int i = blockIdx.x*256 + threadIdx.x;
    if (i >= NB*NH1) return;
    int b = i/NH1, j = i - b*NH1;
    float v = 0.f;
    #pragma unroll
    for (int z = 0; z < SPLITK1; z++) v += g_Cp[(size_t)z*NB*NH1 + i];
    v = v * g_att[b] + b1[j];
    g_C[i] = (v > 0.f) ? v : 0.01f*v;
}

// ---------------- small split-K tiled SGEMM for layer 2 ----------------
template<int SPLITK>
__global__ void __launch_bounds__(256) k_gemm(const float* __restrict__ Bmat, int N, int K){
    const float* A = g_C;
    int n0 = blockIdx.x*64, m0 = blockIdx.y*64, z = blockIdx.z;
    int ck = (K + SPLITK - 1)/SPLITK;
    int k0 = z*ck, kend = min(K, k0 + ck);
    __shared__ float As[64][17], Bs[64][17];
    float acc[4][4];
    #pragma unroll
    for (int mi = 0; mi < 4; mi++)
        #pragma unroll
        for (int ni = 0; ni < 4; ni++) acc[mi][ni] = 0.f;
    int tr = threadIdx.x >> 4, tc = threadIdx.x & 15;
    for (int kt = k0; kt < kend; kt += 16){
        #pragma unroll
        for (int l = 0; l < 4; l++){
            int i = threadIdx.x + l*256;
            int rr = i >> 4, cc = i & 15;
            int k = kt + cc;
            As[rr][cc] = (k < kend) ? A[(size_t)(m0+rr)*K + k] : 0.f;
            int j = n0 + rr;
            Bs[rr][cc] = (k < kend && j < N) ? Bmat[(size_t)j*K + k] : 0.f;
        }
        __syncthreads();
        #pragma unroll
        for (int kk = 0; kk < 16; kk++){
            float a[4], bb[4];
            #pragma unroll
            for (int mi = 0; mi < 4; mi++) a[mi]  = As[tr*4+mi][kk];
            #pragma unroll
            for (int ni = 0; ni < 4; ni++) bb[ni] = Bs[tc*4+ni][kk];
            #pragma unroll
            for (int mi = 0; mi < 4; mi++)
                #pragma unroll
                for (int ni = 0; ni < 4; ni++) acc[mi][ni] = fmaf(a[mi], bb[ni], acc[mi][ni]);
        }
        __syncthreads();
    }
    #pragma unroll
    for (int mi = 0; mi < 4; mi++)
        #pragma unroll
        for (int ni = 0; ni < 4; ni++){
            int m = m0 + tr*4 + mi, n = n0 + tc*4 + ni;
            if (n < N) g_Cp[(size_t)z*NB*N + (size_t)m*N + n] = acc[mi][ni];
        }
}

__global__ void k_comb2(const float* __restrict__ b2){
    int i = blockIdx.x*256 + threadIdx.x;
    if (i >= NB*NO) return;
    int j = i % NO;
    float v = b2[j];
    #pragma unroll
    for (int z = 0; z < 8; z++) v += g_Cp[(size_t)z*NB*NO + i];
    g_x1[i] = v;
}

__global__ void k_head(const float* __restrict__ x, const float* __restrict__ rw,
                       const float* __restrict__ rb, float* __restrict__ out){
    int b = blockIdx.x, t = threadIdx.x;
    float x0 = (x[(size_t)b*SXv*(SYv+1) + t*(SYv+1) + SYv] - 400.0f)*0.01f;
    float v = g_x1[b*NO + t]*rw[2*t] + x0*rw[2*t+1];
    __shared__ float s[128];
    s[t] = v; __syncthreads();
    for (int o = 64; o > 0; o >>= 1){ if (t < o) s[t] += s[t+o]; __syncthreads(); }
    if (t == 0) out[b] = s[0] + rb[0];
}

// ---------------- launch ----------------
extern "C" void kernel_launch(void* const* d_in, const int* in_sizes, int n_in,
                              void* d_out, int out_size){
    const float* x      = (const float*)d_in[0];
    const float* p_w    = (const float*)d_in[1];
    const float* p_b    = (const float*)d_in[2];
    const float* sc0_w1 = (const float*)d_in[3];
    const float* sc0_w2 = (const float*)d_in[4];
    const float* sc1_w1 = (const float*)d_in[5];
    const float* sc1_w2 = (const float*)d_in[6];
    const float* mlp0_w1= (const float*)d_in[7];
    const float* mlp0_b1= (const float*)d_in[8];
    const float* mlp0_w2= (const float*)d_in[9];
    const float* mlp0_b2= (const float*)d_in[10];
    const float* mlp1_w1= (const float*)d_in[11];
    const float* mlp1_b1= (const float*)d_in[12];
    const float* mlp1_w2= (const float*)d_in[13];
    const float* mlp1_b2= (const float*)d_in[14];
    const float* w0_w   = (const float*)d_in[15];
    const float* w0_b   = (const float*)d_in[16];
    const float* w1_w   = (const float*)d_in[17];
    const float* w1_b   = (const float*)d_in[18];
    const float* sa_cw  = (const float*)d_in[19];
    const float* sa_cb  = (const float*)d_in[20];
    const float* sa_fw  = (const float*)d_in[21];
    const float* sa_fb  = (const float*)d_in[22];
    const float* o1_w1  = (const float*)d_in[23];
    const float* o1_b1  = (const float*)d_in[24];
    const float* o1_w2  = (const float*)d_in[25];
    const float* o1_b2  = (const float*)d_in[26];
    const float* reg2_w = (const float*)d_in[27];
    const float* reg2_b = (const float*)d_in[28];
    float* out = (float*)d_out;

    cudaFuncSetAttribute(k_gemm1_mma, cudaFuncAttributeMaxDynamicSharedMemorySize, G1_SMEM);
    cudaFuncSetAttribute(k_conv_tc,  cudaFuncAttributeMaxDynamicSharedMemorySize, CV_SMEM);

    k_twiddle<<<28, 256>>>();

    // Fourier block 0
    k_fdft<<<NB*NC, 256>>>(x, p_w, p_b, 1);
    k_mix<<<NB, 256>>>(sc0_w1, sc0_w2);
    k_idft<<<NB*NC, 256>>>();
    k_fuse<<<dim3((NP+255)/256, NB), 256>>>(mlp0_w1, mlp0_b1, mlp0_w2, mlp0_b2, w0_w, w0_b);

    // Fourier block 1
    k_fdft<<<NB*NC, 256>>>(x, p_w, p_b, 0);
    k_mix<<<NB, 256>>>(sc1_w1, sc1_w2);
    k_idft<<<NB*NC, 256>>>();
    k_fuse<<<dim3((NP+255)/256, NB), 256>>>(mlp1_w1, mlp1_b1, mlp1_w2, mlp1_b2, w1_w, w1_b);

    // spatial attention (tensor-core conv + fused pool)
    k_conv_tc<<<dim3(NTILE, NB), 256, CV_SMEM>>>(sa_cw, sa_cb);
    k_att<<<1, 256>>>(sa_fw, sa_fb);

    // big GEMM on tensor cores (bf16 hi/lo), attention folded into epilogue
    k_gemm1_mma<<<dim3(22, 2, SPLITK1), 256, G1_SMEM>>>(o1_w1);
    k_comb1<<<(NB*NH1+255)/256, 256>>>(o1_b1);
    k_gemm<8><<<dim3(2, 4, 8), 256>>>(o1_w2, NO, 2808);
    k_comb2<<<(NB*NO+255)/256, 256>>>(o1_b2);
    k_head<<<NB, 128>>>(x, reg2_w, reg2_b, out);
}